// round 13
// baseline (speedup 1.0000x reference)
#include <cuda_runtime.h>
#include <cuda_fp16.h>
#include <math.h>
#include <stdint.h>

#define Bz   8
#define Sz   512
#define Dm   512
#define Hn   8
#define DKh  64
#define Lz   6
#define DFFz 2048
#define OUTz 1000
#define NEGV (-1e9f)

// ---------------- scratch (device globals) ----------------
__device__ float g_e[Bz*Sz*Dm];
__device__ __half g_eh[Bz*Sz*Dm];
__device__ __half g_qkvh[3*Bz*Sz*Dm];
__device__ float g_kvf[(size_t)Lz*2*Bz*Sz*Dm];
__device__ float g_attn[Bz*Sz*Dm];
__device__ __half g_hh[Bz*Sz*DFFz];
__device__ float g_t[Bz*Sz*Dm];
__device__ float g_d[Bz*Dm];
__device__ float g_s1[Bz*Dm];
__device__ float g_dq[Bz*Dm];
__device__ float g_dt[Bz*Dm];
__device__ float g_dh[Bz*DFFz];
// fp16 weights in original [K,N] layout
__device__ __half g_wqkvh[Lz*3*Dm*Dm];
__device__ __half g_wf1h[Lz*Dm*DFFz];
__device__ __half g_wf2h[Lz*DFFz*Dm];
__device__ __half g_wd2h[Lz*3*Dm*Dm];

// ---------------- helpers ----------------
__device__ __forceinline__ void cpa16(void* dst, const void* src) {
    uint32_t d = (uint32_t)__cvta_generic_to_shared(dst);
    asm volatile("cp.async.ca.shared.global [%0], [%1], 16;\n" :: "r"(d), "l"(src));
}
#define CP_COMMIT() asm volatile("cp.async.commit_group;\n" ::: "memory")
__device__ __forceinline__ void ldsm4(uint32_t& r0, uint32_t& r1, uint32_t& r2, uint32_t& r3,
                                      const void* p) {
    uint32_t a = (uint32_t)__cvta_generic_to_shared(p);
    asm volatile("ldmatrix.sync.aligned.m8n8.x4.shared.b16 {%0,%1,%2,%3}, [%4];\n"
                 : "=r"(r0), "=r"(r1), "=r"(r2), "=r"(r3) : "r"(a));
}
__device__ __forceinline__ void ldsm4t(uint32_t& r0, uint32_t& r1, uint32_t& r2, uint32_t& r3,
                                       const void* p) {
    uint32_t a = (uint32_t)__cvta_generic_to_shared(p);
    asm volatile("ldmatrix.sync.aligned.m8n8.x4.trans.shared.b16 {%0,%1,%2,%3}, [%4];\n"
                 : "=r"(r0), "=r"(r1), "=r"(r2), "=r"(r3) : "r"(a));
}
__device__ __forceinline__ void mma_f16(float c[4], const uint32_t a[4], const uint32_t b[2]) {
    asm volatile(
        "mma.sync.aligned.m16n8k16.row.col.f32.f16.f16.f32 "
        "{%0,%1,%2,%3}, {%4,%5,%6,%7}, {%8,%9}, {%0,%1,%2,%3};\n"
        : "+f"(c[0]), "+f"(c[1]), "+f"(c[2]), "+f"(c[3])
        : "r"(a[0]), "r"(a[1]), "r"(a[2]), "r"(a[3]), "r"(b[0]), "r"(b[1]));
}

// ---------------- convert 4 weight arrays f32 -> fp16 in one launch ---------
__global__ void convh_all(const float* __restrict__ s0, __half* __restrict__ d0, int n0,
                          const float* __restrict__ s1, __half* __restrict__ d1, int n1,
                          const float* __restrict__ s2, __half* __restrict__ d2, int n2,
                          const float* __restrict__ s3, __half* __restrict__ d3, int n3) {
    int i = blockIdx.x*blockDim.x + threadIdx.x;
    if (i < n0) { d0[i] = __float2half(s0[i]); return; }
    i -= n0;
    if (i < n1) { d1[i] = __float2half(s1[i]); return; }
    i -= n1;
    if (i < n2) { d2[i] = __float2half(s2[i]); return; }
    i -= n2;
    if (i < n3) { d3[i] = __float2half(s3[i]); }
}

// ---------------- embedding + PE ----------------
__global__ void embed_enc(const int* __restrict__ x, const float* __restrict__ emb,
                          float* __restrict__ e, __half* __restrict__ eh) {
    int idx = blockIdx.x*blockDim.x + threadIdx.x;
    if (idx >= Bz*Sz*Dm) return;
    int d  = idx % Dm;
    int bs = idx / Dm;
    int s  = bs % Sz;
    int tok = x[bs];
    float div = exp2f(-(float)(d & ~1) * (13.287712379549449f / (float)Dm));
    float arg = (float)s * div;
    float pe = (d & 1) ? cosf(arg) : sinf(arg);
    float v = emb[tok*Dm + d] * 22.627416997969522f + pe;
    e[idx] = v;
    eh[idx] = __float2half(v);
}

__global__ void embed_dec(const int* __restrict__ tgt, const float* __restrict__ emb,
                          float* __restrict__ o) {
    int idx = blockIdx.x*blockDim.x + threadIdx.x;
    if (idx >= Bz*Dm) return;
    int d = idx % Dm;
    int b = idx / Dm;
    float pe = (d & 1) ? 1.f : 0.f;
    o[idx] = emb[tgt[b]*Dm + d] * 22.627416997969522f + pe;
}

// ============ 3-stage pipelined mma.sync GEMM (fp16, big tiles) =============
template<int BN_, int EPI, int WMODE>
__global__ void __launch_bounds__(BN_ == 128 ? 256 : 128)
gemm_mma(const __half* __restrict__ Ag, const __half* __restrict__ Bg,
         const float* __restrict__ bias,
         float* __restrict__ C, __half* __restrict__ Ch,
         int K, int lda, int ldb, int ldc,
         int zdiv, long long sA1, long long sA2, long long sB1, long long sB2,
         long long sC1, long long sC2, long long sBias1, long long sBias2) {
    constexpr int NT   = (BN_ == 128) ? 256 : 128;
    constexpr int ASTG = 128 * 40;
    constexpr int BLD  = BN_ + 8;
    constexpr int BSTG = 32 * BLD;

    extern __shared__ __half sm[];
    __half* Ah = sm;
    __half* Bh = Ah + 3*ASTG;

    int z = blockIdx.z, z1 = z / zdiv, z2 = z % zdiv;
    const __half* Ab = Ag + z1*sA1 + z2*sA2;
    const __half* Bb = Bg + z1*sB1 + z2*sB2;
    long long coff = z1*sC1 + z2*sC2;

    int m0 = blockIdx.y * 128, n0 = blockIdx.x * BN_;
    int tid = threadIdx.x, lane = tid & 31, wid = tid >> 5;
    int wm = wid & 1, wn = wid >> 1;
    int gid = lane >> 2, tig = lane & 3;

    auto load_stage = [&](int st, int kt) {
        int k0 = kt * 32;
        for (int idx = tid; idx < 512; idx += NT) {
            int r = idx >> 2, c = (idx & 3) * 8;
            cpa16(Ah + st*ASTG + r*40 + c, Ab + (size_t)(m0 + r)*lda + k0 + c);
        }
        constexpr int CH = BN_ / 8;
        for (int idx = tid; idx < 32*CH; idx += NT) {
            int r = idx / CH, c = (idx % CH) * 8;
            cpa16(Bh + st*BSTG + r*BLD + c, Bb + (size_t)(k0 + r)*ldb + n0 + c);
        }
    };

    float acc[4][4][4] = {};
    const int KT = K >> 5;

    load_stage(0, 0); CP_COMMIT();
    if (KT > 1) { load_stage(1, 1); CP_COMMIT(); }
    if (KT > 1) asm volatile("cp.async.wait_group 1;\n" ::: "memory");
    else        asm volatile("cp.async.wait_group 0;\n" ::: "memory");
    __syncthreads();

    for (int c = 0; c < KT; c++) {
        int st = c % 3;
        const __half* a_s = Ah + st*ASTG;
        const __half* b_s = Bh + st*BSTG;

#pragma unroll
        for (int kk = 0; kk < 2; kk++) {
            int kc = kk*16 + ((lane >> 4) << 3);
            uint32_t af[4][4], bf[4][2];
#pragma unroll
            for (int mi = 0; mi < 4; mi++) {
                int ar = wm*64 + mi*16 + (lane & 15);
                ldsm4(af[mi][0], af[mi][1], af[mi][2], af[mi][3], a_s + ar*40 + kc);
            }
#pragma unroll
            for (int ng = 0; ng < 2; ng++) {
                uint32_t r0, r1, r2, r3;
                int rr = kk*16 + ((lane >> 4) << 3) + (lane & 7);
                int cc = wn*32 + ng*16 + (((lane >> 3) & 1) << 3);
                ldsm4t(r0, r1, r2, r3, b_s + rr*BLD + cc);
                bf[ng*2  ][0] = r0; bf[ng*2  ][1] = r2;
                bf[ng*2+1][0] = r1; bf[ng*2+1][1] = r3;
            }
#pragma unroll
            for (int mi = 0; mi < 4; mi++)
#pragma unroll
                for (int ni = 0; ni < 4; ni++) mma_f16(acc[mi][ni], af[mi], bf[ni]);
        }

        if (c + 2 < KT) {
            load_stage((c + 2) % 3, c + 2);
            CP_COMMIT();
            asm volatile("cp.async.wait_group 1;\n" ::: "memory");
            __syncthreads();
        } else if (c + 1 < KT) {
            asm volatile("cp.async.wait_group 0;\n" ::: "memory");
            __syncthreads();
        }
    }

    const float* biasb = (EPI <= 1) ? bias + z1*sBias1 + z2*sBias2 : nullptr;
#pragma unroll
    for (int mi = 0; mi < 4; mi++)
#pragma unroll
        for (int ni = 0; ni < 4; ni++) {
            int row = m0 + wm*64 + mi*16 + gid;
            int col = n0 + wn*32 + ni*8 + tig*2;
#pragma unroll
            for (int e2 = 0; e2 < 4; e2++) {
                int r  = row + (e2 >> 1)*8;
                int cc = col + (e2 & 1);
                float v = acc[mi][ni][e2];
                if (EPI == 0 || EPI == 1) v += biasb[cc];
                if (EPI == 1) v = fmaxf(v, 0.f);
                size_t idx = (size_t)(coff + (long long)r*ldc + cc);
                if (WMODE & 1) C[idx] = v;
                if (WMODE & 2) Ch[idx] = __float2half(v);
            }
        }
}

// ============ fused attention, 512 threads (16 warps: 4m x 4n) ==============
__global__ void __launch_bounds__(512)
attn_fused(const __half* __restrict__ qh, const __half* __restrict__ kh,
           const __half* __restrict__ vh, float* __restrict__ attn) {
    extern __shared__ __half sm[];
    __half* Qs = sm;                        // [64][72]
    __half* Ks = sm + 64*72;                // [512][72]
    __half* Ps = sm;                        // [64][520]  (phase 2 overlay)
    __half* Vs = sm + 64*520;               // [512][72]  (phase 2)
    float* rmax = (float*)(sm + 70144);     // [64][4]
    float* rsum = rmax + 256;               // [64][4]

    int bh = blockIdx.y, b = bh >> 3, h = bh & 7;
    int q0 = blockIdx.x * 64;
    int tid = threadIdx.x, lane = tid & 31, wid = tid >> 5;
    int wm = wid & 3, wn = wid >> 2;        // 4 x 4
    int gid = lane >> 2, tig = lane & 3;

    {
        int r = tid >> 3, c = (tid & 7) * 8;
        cpa16(Qs + r*72 + c, qh + (size_t)(b*Sz + q0 + r)*Dm + h*DKh + c);
    }
    for (int idx = tid; idx < 4096; idx += 512) {
        int r = idx >> 3, c = (idx & 7) * 8;
        cpa16(Ks + r*72 + c, kh + (size_t)(b*Sz + r)*Dm + h*DKh + c);
    }
    CP_COMMIT();
    asm volatile("cp.async.wait_group 0;\n" ::: "memory");
    __syncthreads();

    // ---- phase 1: S = Q K^T (warp: 16 rows x 128 cols) ----
    float acc[16][4] = {};
#pragma unroll
    for (int kk = 0; kk < 4; kk++) {
        int kc = kk*16 + ((lane >> 4) << 3);
        uint32_t af[4];
        int ar = wm*16 + (lane & 15);
        ldsm4(af[0], af[1], af[2], af[3], Qs + ar*72 + kc);
#pragma unroll
        for (int ng = 0; ng < 8; ng++) {
            int br = wn*128 + ng*16 + (lane & 15);
            uint32_t r0, r1, r2, r3;
            ldsm4(r0, r1, r2, r3, Ks + br*72 + kc);
            uint32_t bf0[2] = {r0, r2}, bf1[2] = {r1, r3};
            mma_f16(acc[ng*2  ], af, bf0);
            mma_f16(acc[ng*2+1], af, bf1);
        }
    }
    __syncthreads();          // Qs/Ks dead

    // ---- V loads (overlap with softmax) ----
    for (int idx = tid; idx < 4096; idx += 512) {
        int r = idx >> 3, c = (idx & 7) * 8;
        cpa16(Vs + r*72 + c, vh + (size_t)(b*Sz + r)*Dm + h*DKh + c);
    }
    CP_COMMIT();

    // ---- softmax over regs ----
#pragma unroll
    for (int rh = 0; rh < 2; rh++) {
        float m1 = -INFINITY;
#pragma unroll
        for (int ni = 0; ni < 16; ni++)
#pragma unroll
            for (int nj = 0; nj < 2; nj++) {
                float v = acc[ni][rh*2+nj] * 0.125f;
                if (v == 0.f) v = NEGV;
                acc[ni][rh*2+nj] = v;
                m1 = fmaxf(m1, v);
            }
        m1 = fmaxf(m1, __shfl_xor_sync(0xffffffffu, m1, 1));
        m1 = fmaxf(m1, __shfl_xor_sync(0xffffffffu, m1, 2));
        int row = wm*16 + rh*8 + gid;
        if (tig == 0) rmax[row*4 + wn] = m1;
    }
    __syncthreads();
#pragma unroll
    for (int rh = 0; rh < 2; rh++) {
        int row = wm*16 + rh*8 + gid;
        float mx = fmaxf(fmaxf(rmax[row*4+0], rmax[row*4+1]),
                         fmaxf(rmax[row*4+2], rmax[row*4+3]));
        float s1 = 0.f;
#pragma unroll
        for (int ni = 0; ni < 16; ni++)
#pragma unroll
            for (int nj = 0; nj < 2; nj++) {
                float v = __expf(acc[ni][rh*2+nj] - mx);
                acc[ni][rh*2+nj] = v;
                s1 += v;
            }
        s1 += __shfl_xor_sync(0xffffffffu, s1, 1);
        s1 += __shfl_xor_sync(0xffffffffu, s1, 2);
        if (tig == 0) rsum[row*4 + wn] = s1;
    }
    __syncthreads();
    // ---- write P (fp16) into smem ----
#pragma unroll
    for (int rh = 0; rh < 2; rh++) {
        int row = wm*16 + rh*8 + gid;
        float inv = 1.f / (rsum[row*4+0] + rsum[row*4+1] + rsum[row*4+2] + rsum[row*4+3]);
#pragma unroll
        for (int ni = 0; ni < 16; ni++) {
            int col = wn*128 + ni*8 + tig*2;
            __half2 hv = __floats2half2_rn(acc[ni][rh*2+0] * inv,
                                           acc[ni][rh*2+1] * inv);
            *(__half2*)(Ps + row*520 + col) = hv;
        }
    }
    asm volatile("cp.async.wait_group 0;\n" ::: "memory");
    __syncthreads();

    // ---- phase 2: O = P V  (warp: 16 rows x 16 cols) ----
    float o[2][4] = {};
#pragma unroll 4
    for (int kk = 0; kk < 32; kk++) {
        int kc = kk*16 + ((lane >> 4) << 3);
        uint32_t af[4];
        int ar = wm*16 + (lane & 15);
        ldsm4(af[0], af[1], af[2], af[3], Ps + ar*520 + kc);
        uint32_t r0, r1, r2, r3;
        int rr = kk*16 + ((lane >> 4) << 3) + (lane & 7);
        int cc = wn*16 + (((lane >> 3) & 1) << 3);
        ldsm4t(r0, r1, r2, r3, Vs + rr*72 + cc);
        uint32_t bf0[2] = {r0, r2}, bf1[2] = {r1, r3};
        mma_f16(o[0], af, bf0);
        mma_f16(o[1], af, bf1);
    }

#pragma unroll
    for (int n8 = 0; n8 < 2; n8++) {
        int row = q0 + wm*16 + gid;
        int col = h*DKh + wn*16 + n8*8 + tig*2;
#pragma unroll
        for (int e2 = 0; e2 < 4; e2++) {
            int r  = row + (e2 >> 1)*8;
            int cc = col + (e2 & 1);
            attn[(size_t)(b*Sz + r)*Dm + cc] = o[n8][e2];
        }
    }
}

// ---------------- out = LayerNorm(a + res) (+ optional fp16 copy) -----------
template<int H16>
__global__ void add_ln(const float* __restrict__ a, const float* __restrict__ res,
                       const float* __restrict__ g, const float* __restrict__ beta,
                       float* __restrict__ out, __half* __restrict__ oh) {
    size_t row = blockIdx.x;
    int tid = threadIdx.x;
    int c = tid * 4;
    float4 av = *(const float4*)&a[row*Dm + c];
    float4 rv = *(const float4*)&res[row*Dm + c];
    float4 x;
    x.x = av.x + rv.x; x.y = av.y + rv.y; x.z = av.z + rv.z; x.w = av.w + rv.w;
    float s  = x.x + x.y + x.z + x.w;
    float s2 = x.x*x.x + x.y*x.y + x.z*x.z + x.w*x.w;
#pragma unroll
    for (int o = 16; o; o >>= 1) {
        s  += __shfl_xor_sync(0xffffffffu, s,  o);
        s2 += __shfl_xor_sync(0xffffffffu, s2, o);
    }
    __shared__ float sm[4], sq[4];
    if ((tid & 31) == 0) { sm[tid>>5] = s; sq[tid>>5] = s2; }
    __syncthreads();
    s  = sm[0] + sm[1] + sm[2] + sm[3];
    s2 = sq[0] + sq[1] + sq[2] + sq[3];
    float mean = s * (1.f/Dm);
    float var  = s2 * (1.f/Dm) - mean*mean;
    float inv  = rsqrtf(var + 1e-5f);
    float4 gv = *(const float4*)&g[c];
    float4 bv = *(const float4*)&beta[c];
    float y[4];
    y[0] = (x.x - mean)*inv*gv.x + bv.x;
    y[1] = (x.y - mean)*inv*gv.y + bv.y;
    y[2] = (x.z - mean)*inv*gv.z + bv.z;
    y[3] = (x.w - mean)*inv*gv.w + bv.w;
    *(float4*)&out[row*Dm + c] = *(float4*)y;
    if (H16) {
        __half2 h0 = __floats2half2_rn(y[0], y[1]);
        __half2 h1 = __floats2half2_rn(y[2], y[3]);
        *(__half2*)&oh[row*Dm + c]     = h0;
        *(__half2*)&oh[row*Dm + c + 2] = h1;
    }
}

// ---------------- decoder cross-attention (Sq=1, f32) ----------------
__global__ void cross_attn(const float* __restrict__ q, const float* __restrict__ k,
                           const float* __restrict__ v, float* __restrict__ o) {
    int h = blockIdx.x, b = blockIdx.y;
    __shared__ float qv[64];
    __shared__ float p[512];
    __shared__ float red[8];
    int tid = threadIdx.x;
    if (tid < 64) qv[tid] = q[b*Dm + h*DKh + tid];
    __syncthreads();
    float sc[2];
    float lmax = -INFINITY;
#pragma unroll
    for (int it = 0; it < 2; it++) {
        int j = tid + it*256;
        const float* kp = &k[(size_t)(b*Sz + j)*Dm + h*DKh];
        float s = 0.f;
#pragma unroll
        for (int c = 0; c < 64; c++) s += qv[c] * kp[c];
        s *= 0.125f;
        if (s == 0.f) s = NEGV;
        sc[it] = s;
        lmax = fmaxf(lmax, s);
    }
#pragma unroll
    for (int off = 16; off; off >>= 1) lmax = fmaxf(lmax, __shfl_xor_sync(0xffffffffu, lmax, off));
    if ((tid & 31) == 0) red[tid >> 5] = lmax;
    __syncthreads();
    float mx = red[0];
#pragma unroll
    for (int w = 1; w < 8; w++) mx = fmaxf(mx, red[w]);
    __syncthreads();
    float lsum = 0.f;
#pragma unroll
    for (int it = 0; it < 2; it++) {
        float e = __expf(sc[it] - mx);
        p[tid + it*256] = e;
        lsum += e;
    }
#pragma unroll
    for (int off = 16; off; off >>= 1) lsum += __shfl_xor_sync(0xffffffffu, lsum, off);
    if ((tid & 31) == 0) red[tid >> 5] = lsum;
    __syncthreads();
    float sum = red[0] + red[1] + red[2] + red[3] + red[4] + red[5] + red[6] + red[7];
    float inv = 1.f / sum;
    int warp = tid >> 5, lane = tid & 31;
#pragma unroll
    for (int dd = 0; dd < 8; dd++) {
        int d = warp*8 + dd;
        float acc = 0.f;
        for (int j = lane; j < Sz; j += 32)
            acc += p[j] * v[(size_t)(b*Sz + j)*Dm + h*DKh + d];
#pragma unroll
        for (int off = 16; off; off >>= 1) acc += __shfl_xor_sync(0xffffffffu, acc, off);
        if (lane == 0) o[b*Dm + h*DKh + d] = acc * inv;
    }
}

// ---------- tiny-M (M=8) GEMM, K-parallel: 512 thr = 64 cols x 8 K-slices ---
template<int RELU>
__global__ void __launch_bounds__(512)
gemm8w(const float* __restrict__ A, const float* __restrict__ W,
       const float* __restrict__ bias, float* __restrict__ C, int K, int N) {
    __shared__ float red[8][8][64];
    int t = threadIdx.x;
    int cl = t & 63;
    int col = blockIdx.x*64 + cl;
    int sl = t >> 6;
    float acc[8] = {};
    if (col < N) {
        int kn = K >> 3;
        int k0 = sl * kn, k1 = k0 + kn;
        for (int k = k0; k < k1; k++) {
            float wv = W[(size_t)k*N + col];
#pragma unroll
            for (int r = 0; r < 8; r++) acc[r] += A[r*K + k] * wv;
        }
    }
#pragma unroll
    for (int r = 0; r < 8; r++) red[r][sl][cl] = acc[r];
    __syncthreads();
    if (t < 64 && col < N) {
        float bv = bias[col];
#pragma unroll
        for (int r = 0; r < 8; r++) {
            float s = 0.f;
#pragma unroll
            for (int s8 = 0; s8 < 8; s8++) s += red[r][s8][t];
            float val = s + bv;
            if (RELU) val = fmaxf(val, 0.f);
            C[r*N + col] = val;
        }
    }
}

// ---------- fused LN + tiny-M GEMM: y = LN(a+res); state_out = y; C = y@W ---
// NO ARGUMENT MAY ALIAS: a, res, state_out, C must all be distinct buffers.
// Every CTA recomputes the 8x512 LN (cheap, redundant, race-free).
template<int RELU>
__global__ void __launch_bounds__(512)
gemm8w_ln(const float* __restrict__ a, const float* __restrict__ res,
          const float* __restrict__ g, const float* __restrict__ beta,
          float* __restrict__ state_out,
          const float* __restrict__ W, const float* __restrict__ bias,
          float* __restrict__ C, int N) {
    __shared__ float As[8][512];
    __shared__ float red[8][8][64];
    __shared__ float rs[16], rq[16];
    int t = threadIdx.x, lane = t & 31, wid = t >> 5;
    {
        int r = t >> 6, cb = (t & 63) * 8;
        float x[8];
        float s = 0.f, s2 = 0.f;
#pragma unroll
        for (int j = 0; j < 8; j++) {
            x[j] = a[r*Dm + cb + j] + res[r*Dm + cb + j];
            s += x[j]; s2 += x[j]*x[j];
        }
#pragma unroll
        for (int o = 16; o; o >>= 1) {
            s  += __shfl_xor_sync(0xffffffffu, s,  o);
            s2 += __shfl_xor_sync(0xffffffffu, s2, o);
        }
        if (lane == 0) { rs[wid] = s; rq[wid] = s2; }
        __syncthreads();
        s  = rs[r*2] + rs[r*2+1];
        s2 = rq[r*2] + rq[r*2+1];
        float mean = s * (1.f/Dm);
        float var  = s2 * (1.f/Dm) - mean*mean;
        float inv  = rsqrtf(var + 1e-5f);
#pragma unroll
        for (int j = 0; j < 8; j++) {
            float y = (x[j] - mean)*inv*g[cb+j] + beta[cb+j];
            As[r][cb+j] = y;
            state_out[r*Dm + cb + j] = y;
        }
    }
    __syncthreads();
    int cl = t & 63;
    int col = blockIdx.x*64 + cl;
    int sl = t >> 6;
    float acc[8] = {};
    if (col < N) {
        int k0 = sl * 64, k1 = k0 + 64;
        for (int k = k0; k < k1; k++) {
            float wv = W[(size_t)k*N + col];
#pragma unroll
            for (int r = 0; r < 8; r++) acc[r] += As[r][k] * wv;
        }
    }
#pragma unroll
    for (int r = 0; r < 8; r++) red[r][sl][cl] = acc[r];
    __syncthreads();
    if (t < 64 && col < N) {
        float bv = bias[col];
#pragma unroll
        for (int r = 0; r < 8; r++) {
            float s = 0.f;
#pragma unroll
            for (int s8 = 0; s8 < 8; s8++) s += red[r][s8][t];
            float val = s + bv;
            if (RELU) val = fmaxf(val, 0.f);
            C[r*N + col] = val;
        }
    }
}

// ---------------- host orchestration ----------------
extern "C" void kernel_launch(void* const* d_in, const int* in_sizes, int n_in,
                              void* d_out, int out_size) {
    const int*   x        = (const int*)d_in[0];
    const int*   tgt      = (const int*)d_in[1];
    const float* in_emb   = (const float*)d_in[2];
    const float* out_emb  = (const float*)d_in[3];
    const float* enc_qkv_w = (const float*)d_in[4];
    const float* enc_qkv_b = (const float*)d_in[5];
    const float* enc_ln1_g = (const float*)d_in[6];
    const float* enc_ln1_b = (const float*)d_in[7];
    const float* enc_ffn1_w = (const float*)d_in[8];
    const float* enc_ffn1_b = (const float*)d_in[9];
    const float* enc_ffn2_w = (const float*)d_in[10];
    const float* enc_ffn2_b = (const float*)d_in[11];
    const float* enc_ln2_g = (const float*)d_in[12];
    const float* enc_ln2_b = (const float*)d_in[13];
    const float* dec_qkv1_w = (const float*)d_in[14];
    const float* dec_qkv1_b = (const float*)d_in[15];
    const float* dec_ln1_g = (const float*)d_in[16];
    const float* dec_ln1_b = (const float*)d_in[17];
    const float* dec_qkv2_w = (const float*)d_in[18];
    const float* dec_qkv2_b = (const float*)d_in[19];
    const float* dec_ln2_g = (const float*)d_in[20];
    const float* dec_ln2_b = (const float*)d_in[21];
    const float* dec_ffn1_w = (const float*)d_in[22];
    const float* dec_ffn1_b = (const float*)d_in[23];
    const float* dec_ffn2_w = (const float*)d_in[24];
    const float* dec_ffn2_b = (const float*)d_in[25];
    const float* dec_ln3_g = (const float*)d_in[26];
    const float* dec_ln3_b = (const float*)d_in[27];
    const float* out_w = (const float*)d_in[28];
    const float* out_b = (const float*)d_in[29];

    float *e, *attn, *tbuf, *s0, *s1b, *dq, *dt, *dh, *kvf;
    __half *eh, *qkvh, *hh, *wqkvh, *wf1h, *wf2h, *wd2h;
    cudaGetSymbolAddress((void**)&e,    g_e);
    cudaGetSymbolAddress((void**)&eh,   g_eh);
    cudaGetSymbolAddress((void**)&qkvh, g_qkvh);
    cudaGetSymbolAddress((void**)&kvf,  g_kvf);
    cudaGetSymbolAddress((void**)&attn, g_attn);
    cudaGetSymbolAddress((void**)&hh,   g_hh);
    cudaGetSymbolAddress((void**)&tbuf, g_t);
    cudaGetSymbolAddress((void**)&s0,   g_d);
    cudaGetSymbolAddress((void**)&s1b,  g_s1);
    cudaGetSymbolAddress((void**)&dq,   g_dq);
    cudaGetSymbolAddress((void**)&dt,   g_dt);
    cudaGetSymbolAddress((void**)&dh,   g_dh);
    cudaGetSymbolAddress((void**)&wqkvh, g_wqkvh);
    cudaGetSymbolAddress((void**)&wf1h, g_wf1h);
    cudaGetSymbolAddress((void**)&wf2h, g_wf2h);
    cudaGetSymbolAddress((void**)&wd2h, g_wd2h);

    const int M = Bz*Sz;            // 4096
    const long long DD = (long long)Dm*Dm;
    const long long MD = (long long)M*Dm;

    const int SM_G128 = 30720 + 3*32*136*2;   // 56832
    const int SM_G64  = 30720 + 3*32*72*2;    // 44544
    const int SM_AT   = 70144*2 + 2048;       // 142336
    cudaFuncSetAttribute(gemm_mma<128,0,2>, cudaFuncAttributeMaxDynamicSharedMemorySize, SM_G128);
    cudaFuncSetAttribute(gemm_mma<128,1,2>, cudaFuncAttributeMaxDynamicSharedMemorySize, SM_G128);
    cudaFuncSetAttribute(gemm_mma<128,0,1>, cudaFuncAttributeMaxDynamicSharedMemorySize, SM_G128);
    cudaFuncSetAttribute(gemm_mma<64,0,1>,  cudaFuncAttributeMaxDynamicSharedMemorySize, SM_G64);
    cudaFuncSetAttribute(attn_fused,        cudaFuncAttributeMaxDynamicSharedMemorySize, SM_AT);

    // ---- convert all weights once, in a single launch ----
    {
        int n1 = Lz*3*Dm*Dm;
        int n2 = Lz*Dm*DFFz;
        long long total = 2LL*n1 + 2LL*n2;
        convh_all<<<(int)((total + 255)/256), 256>>>(
            enc_qkv_w, wqkvh, n1,
            enc_ffn1_w, wf1h, n2,
            enc_ffn2_w, wf2h, n2,
            dec_qkv2_w, wd2h, n1);
    }

    // ---------------- encoder ----------------
    embed_enc<<<(Bz*Sz*Dm + 255)/256, 256>>>(x, in_emb, e, eh);
    for (int i = 0; i < Lz; i++) {
        gemm_mma<128,0,2><<<dim3(Dm/128, M/128, 3), 256, SM_G128>>>(
            eh, wqkvh + (size_t)i*3*DD,
            enc_qkv_b + (size_t)i*3*Dm, nullptr, qkvh,
            Dm, Dm, Dm, Dm,
            1, 0, 0, DD, 0, MD, 0, Dm, 0);
        attn_fused<<<dim3(Sz/64, Bz*Hn), 512, SM_AT>>>(
            qkvh, qkvh + MD, qkvh + 2*MD, attn);
        add_ln<1><<<M, 128>>>(attn, e, enc_ln1_g + i*Dm, enc_ln1_b + i*Dm, e, eh);
        gemm_mma<128,1,2><<<dim3(DFFz/128, M/128, 1), 256, SM_G128>>>(
            eh, wf1h + (size_t)i*Dm*DFFz,
            enc_ffn1_b + (size_t)i*DFFz, nullptr, hh,
            Dm, Dm, DFFz, DFFz,
            1, 0, 0, 0, 0, 0, 0, 0, 0);
        gemm_mma<64,0,1><<<dim3(Dm/64, M/128, 1), 128, SM_G64>>>(
            hh, wf2h + (size_t)i*DFFz*Dm,
            enc_ffn2_b + (size_t)i*Dm, tbuf, nullptr,
            DFFz, DFFz, Dm, Dm,
            1, 0, 0, 0, 0, 0, 0, 0, 0);
        add_ln<1><<<M, 128>>>(tbuf, e, enc_ln2_g + i*Dm, enc_ln2_b + i*Dm, e, eh);
    }

    // ---- batched decoder cross K/V for ALL layers: z = Lz*2 = 12 ----
    gemm_mma<128,0,1><<<dim3(Dm/128, M/128, Lz*2), 256, SM_G128>>>(
        eh, wd2h + DD,
        dec_qkv2_b + Dm, kvf, nullptr,
        Dm, Dm, Dm, Dm,
        2, 0, 0, 3*DD, DD, 2*MD, MD, 3*(long long)Dm, Dm);

    // ---------------- decoder (seq len 1; self-attn == V projection) --------
    // State ping-pongs between s0/s1b; no call aliases its output with inputs.
    float* s  = s0;
    float* ns = s1b;
    embed_dec<<<(Bz*Dm + 255)/256, 256>>>(tgt, out_emb, s);
    for (int i = 0; i < Lz; i++) {
        if (i == 0) {
            // dh = V-proj(s)
            gemm8w<0><<<Dm/64, 512>>>(s, dec_qkv1_w + (size_t)(i*3+2)*DD,
                                      dec_qkv1_b + (i*3+2)*Dm, dh, Dm, Dm);
        } else {
            // ns = LN3_{i-1}(dt + s); dh = V-proj(ns)
            gemm8w_ln<0><<<Dm/64, 512>>>(dt, s, dec_ln3_g + (i-1)*Dm, dec_ln3_b + (i-1)*Dm,
                                         ns, dec_qkv1_w + (size_t)(i*3+2)*DD,
                                         dec_qkv1_b + (i*3+2)*Dm, dh, Dm);
            float* tmp = s; s = ns; ns = tmp;
        }
        // ns = LN1(dh + s); dq = q-proj(ns)
        gemm8w_ln<0><<<Dm/64, 512>>>(dh, s, dec_ln1_g + i*Dm, dec_ln1_b + i*Dm,
                                     ns, dec_qkv2_w + (size_t)(i*3+0)*DD,
                                     dec_qkv2_b + (i*3+0)*Dm, dq, Dm);
        { float* tmp = s; s = ns; ns = tmp; }
        cross_attn<<<dim3(Hn, Bz), 256>>>(dq, kvf + (size_t)i*2*MD, kvf + (size_t)i*2*MD + MD, dt);
        // ns = LN2(dt + s); dh = relu(FFN1(ns))
        gemm8w_ln<1><<<DFFz/64, 512>>>(dt, s, dec_ln2_g + i*Dm, dec_ln2_b + i*Dm,
                                       ns, dec_ffn1_w + (size_t)i*Dm*DFFz,
                                       dec_ffn1_b + i*DFFz, dh, DFFz);
        { float* tmp = s; s = ns; ns = tmp; }
        // dt = FFN2(dh)
        gemm8w<0><<<Dm/64, 512>>>(dh, dec_ffn2_w + (size_t)i*DFFz*Dm,
                                  dec_ffn2_b + i*Dm, dt, DFFz, Dm);
    }
    // final: ns = LN3_{L-1}(dt + s); d_out = out-proj(ns)
    gemm8w_ln<0><<<(OUTz+63)/64, 512>>>(dt, s, dec_ln3_g + (Lz-1)*Dm, dec_ln3_b + (Lz-1)*Dm,
                                        ns, out_w, out_b, (float*)d_out, OUTz);
    (void)in_sizes; (void)n_in; (void)out_size;
}

// round 15
// speedup vs baseline: 1.0234x; 1.0234x over previous
#include <cuda_runtime.h>
#include <cuda_fp16.h>
#include <math.h>
#include <stdint.h>

#define Bz   8
#define Sz   512
#define Dm   512
#define Hn   8
#define DKh  64
#define Lz   6
#define DFFz 2048
#define OUTz 1000
#define NEGV (-1e9f)

// ---------------- scratch (device globals) ----------------
__device__ float g_e[Bz*Sz*Dm];
__device__ __half g_eh[Bz*Sz*Dm];
__device__ __half g_qkvh[3*Bz*Sz*Dm];
__device__ float g_kvf[(size_t)Lz*2*Bz*Sz*Dm];
__device__ float g_attn[Bz*Sz*Dm];
__device__ __half g_hh[Bz*Sz*DFFz];
__device__ float g_t[Bz*Sz*Dm];
__device__ float g_d[Bz*Dm];
__device__ float g_s1[Bz*Dm];
__device__ float g_dq[Bz*Dm];
__device__ float g_dt[Bz*Dm];
__device__ float g_dh[Bz*DFFz];
// fp16 weights in original [K,N] layout
__device__ __half g_wqkvh[Lz*3*Dm*Dm];
__device__ __half g_wf1h[Lz*Dm*DFFz];
__device__ __half g_wf2h[Lz*DFFz*Dm];
__device__ __half g_wd2h[Lz*3*Dm*Dm];

// ---------------- helpers ----------------
__device__ __forceinline__ void cpa16(void* dst, const void* src) {
    uint32_t d = (uint32_t)__cvta_generic_to_shared(dst);
    asm volatile("cp.async.ca.shared.global [%0], [%1], 16;\n" :: "r"(d), "l"(src));
}
#define CP_COMMIT() asm volatile("cp.async.commit_group;\n" ::: "memory")
__device__ __forceinline__ void ldsm4(uint32_t& r0, uint32_t& r1, uint32_t& r2, uint32_t& r3,
                                      const void* p) {
    uint32_t a = (uint32_t)__cvta_generic_to_shared(p);
    asm volatile("ldmatrix.sync.aligned.m8n8.x4.shared.b16 {%0,%1,%2,%3}, [%4];\n"
                 : "=r"(r0), "=r"(r1), "=r"(r2), "=r"(r3) : "r"(a));
}
__device__ __forceinline__ void ldsm4t(uint32_t& r0, uint32_t& r1, uint32_t& r2, uint32_t& r3,
                                       const void* p) {
    uint32_t a = (uint32_t)__cvta_generic_to_shared(p);
    asm volatile("ldmatrix.sync.aligned.m8n8.x4.trans.shared.b16 {%0,%1,%2,%3}, [%4];\n"
                 : "=r"(r0), "=r"(r1), "=r"(r2), "=r"(r3) : "r"(a));
}
__device__ __forceinline__ void mma_f16(float c[4], const uint32_t a[4], const uint32_t b[2]) {
    asm volatile(
        "mma.sync.aligned.m16n8k16.row.col.f32.f16.f16.f32 "
        "{%0,%1,%2,%3}, {%4,%5,%6,%7}, {%8,%9}, {%0,%1,%2,%3};\n"
        : "+f"(c[0]), "+f"(c[1]), "+f"(c[2]), "+f"(c[3])
        : "r"(a[0]), "r"(a[1]), "r"(a[2]), "r"(a[3]), "r"(b[0]), "r"(b[1]));
}

// ---------------- convert 4 weight arrays f32 -> fp16 in one launch ---------
__global__ void convh_all(const float* __restrict__ s0, __half* __restrict__ d0, int n0,
                          const float* __restrict__ s1, __half* __restrict__ d1, int n1,
                          const float* __restrict__ s2, __half* __restrict__ d2, int n2,
                          const float* __restrict__ s3, __half* __restrict__ d3, int n3) {
    int i = blockIdx.x*blockDim.x + threadIdx.x;
    if (i < n0) { d0[i] = __float2half(s0[i]); return; }
    i -= n0;
    if (i < n1) { d1[i] = __float2half(s1[i]); return; }
    i -= n1;
    if (i < n2) { d2[i] = __float2half(s2[i]); return; }
    i -= n2;
    if (i < n3) { d3[i] = __float2half(s3[i]); }
}

// ---------------- embedding + PE ----------------
__global__ void embed_enc(const int* __restrict__ x, const float* __restrict__ emb,
                          float* __restrict__ e, __half* __restrict__ eh) {
    int idx = blockIdx.x*blockDim.x + threadIdx.x;
    if (idx >= Bz*Sz*Dm) return;
    int d  = idx % Dm;
    int bs = idx / Dm;
    int s  = bs % Sz;
    int tok = x[bs];
    float div = exp2f(-(float)(d & ~1) * (13.287712379549449f / (float)Dm));
    float arg = (float)s * div;
    float pe = (d & 1) ? cosf(arg) : sinf(arg);
    float v = emb[tok*Dm + d] * 22.627416997969522f + pe;
    e[idx] = v;
    eh[idx] = __float2half(v);
}

__global__ void embed_dec(const int* __restrict__ tgt, const float* __restrict__ emb,
                          float* __restrict__ o) {
    int idx = blockIdx.x*blockDim.x + threadIdx.x;
    if (idx >= Bz*Dm) return;
    int d = idx % Dm;
    int b = idx / Dm;
    float pe = (d & 1) ? 1.f : 0.f;
    o[idx] = emb[tgt[b]*Dm + d] * 22.627416997969522f + pe;
}

// ========== persistent 3-stage pipelined mma.sync GEMM (fp16) ===============
// Flattened tile loop over (gz, gy, gx); launch grid = min(total, cap).
template<int BN_, int EPI, int WMODE>
__global__ void __launch_bounds__(BN_ == 128 ? 256 : 128)
gemm_mma(const __half* __restrict__ Ag, const __half* __restrict__ Bg,
         const float* __restrict__ bias,
         float* __restrict__ C, __half* __restrict__ Ch,
         int K, int lda, int ldb, int ldc,
         int gx, int gy, int gz,
         int zdiv, long long sA1, long long sA2, long long sB1, long long sB2,
         long long sC1, long long sC2, long long sBias1, long long sBias2) {
    constexpr int NT   = (BN_ == 128) ? 256 : 128;
    constexpr int ASTG = 128 * 40;
    constexpr int BLD  = BN_ + 8;
    constexpr int BSTG = 32 * BLD;

    extern __shared__ __half sm[];
    __half* Ah = sm;
    __half* Bh = Ah + 3*ASTG;

    int tid = threadIdx.x, lane = tid & 31, wid = tid >> 5;
    int wm = wid & 1, wn = wid >> 1;
    int gid = lane >> 2, tig = lane & 3;
    const int KT = K >> 5;
    const int total = gx * gy * gz;

    for (int t = blockIdx.x; t < total; t += gridDim.x) {
        int z  = t / (gx * gy);
        int rem = t - z * gx * gy;
        int ty = rem / gx, tx = rem - ty * gx;
        int m0 = ty * 128, n0 = tx * BN_;
        int z1 = z / zdiv, z2 = z % zdiv;
        const __half* Ab = Ag + z1*sA1 + z2*sA2;
        const __half* Bb = Bg + z1*sB1 + z2*sB2;
        long long coff = z1*sC1 + z2*sC2;

        auto load_stage = [&](int st, int kt) {
            int k0 = kt * 32;
            for (int idx = tid; idx < 512; idx += NT) {
                int r = idx >> 2, c = (idx & 3) * 8;
                cpa16(Ah + st*ASTG + r*40 + c, Ab + (size_t)(m0 + r)*lda + k0 + c);
            }
            constexpr int CH = BN_ / 8;
            for (int idx = tid; idx < 32*CH; idx += NT) {
                int r = idx / CH, c = (idx % CH) * 8;
                cpa16(Bh + st*BSTG + r*BLD + c, Bb + (size_t)(k0 + r)*ldb + n0 + c);
            }
        };

        float acc[4][4][4] = {};

        load_stage(0, 0); CP_COMMIT();
        if (KT > 1) { load_stage(1, 1); CP_COMMIT(); }
        if (KT > 1) asm volatile("cp.async.wait_group 1;\n" ::: "memory");
        else        asm volatile("cp.async.wait_group 0;\n" ::: "memory");
        __syncthreads();

        for (int c = 0; c < KT; c++) {
            int st = c % 3;
            const __half* a_s = Ah + st*ASTG;
            const __half* b_s = Bh + st*BSTG;

#pragma unroll
            for (int kk = 0; kk < 2; kk++) {
                int kc = kk*16 + ((lane >> 4) << 3);
                uint32_t af[4][4], bf[4][2];
#pragma unroll
                for (int mi = 0; mi < 4; mi++) {
                    int ar = wm*64 + mi*16 + (lane & 15);
                    ldsm4(af[mi][0], af[mi][1], af[mi][2], af[mi][3], a_s + ar*40 + kc);
                }
#pragma unroll
                for (int ng = 0; ng < 2; ng++) {
                    uint32_t r0, r1, r2, r3;
                    int rr = kk*16 + ((lane >> 4) << 3) + (lane & 7);
                    int cc = wn*32 + ng*16 + (((lane >> 3) & 1) << 3);
                    ldsm4t(r0, r1, r2, r3, b_s + rr*BLD + cc);
                    bf[ng*2  ][0] = r0; bf[ng*2  ][1] = r2;
                    bf[ng*2+1][0] = r1; bf[ng*2+1][1] = r3;
                }
#pragma unroll
                for (int mi = 0; mi < 4; mi++)
#pragma unroll
                    for (int ni = 0; ni < 4; ni++) mma_f16(acc[mi][ni], af[mi], bf[ni]);
            }

            if (c + 2 < KT) {
                load_stage((c + 2) % 3, c + 2);
                CP_COMMIT();
                asm volatile("cp.async.wait_group 1;\n" ::: "memory");
                __syncthreads();
            } else if (c + 1 < KT) {
                asm volatile("cp.async.wait_group 0;\n" ::: "memory");
                __syncthreads();
            }
        }

        const float* biasb = (EPI <= 1) ? bias + z1*sBias1 + z2*sBias2 : nullptr;
#pragma unroll
        for (int mi = 0; mi < 4; mi++)
#pragma unroll
            for (int ni = 0; ni < 4; ni++) {
                int row = m0 + wm*64 + mi*16 + gid;
                int col = n0 + wn*32 + ni*8 + tig*2;
#pragma unroll
                for (int e2 = 0; e2 < 4; e2++) {
                    int r  = row + (e2 >> 1)*8;
                    int cc = col + (e2 & 1);
                    float v = acc[mi][ni][e2];
                    if (EPI == 0 || EPI == 1) v += biasb[cc];
                    if (EPI == 1) v = fmaxf(v, 0.f);
                    size_t idx = (size_t)(coff + (long long)r*ldc + cc);
                    if (WMODE & 1) C[idx] = v;
                    if (WMODE & 2) Ch[idx] = __float2half(v);
                }
            }
        __syncthreads();   // epilogue done before next tile overwrites smem
    }
}

// ============ fused attention, 512 threads (16 warps: 4m x 4n) ==============
__global__ void __launch_bounds__(512)
attn_fused(const __half* __restrict__ qh, const __half* __restrict__ kh,
           const __half* __restrict__ vh, float* __restrict__ attn) {
    extern __shared__ __half sm[];
    __half* Qs = sm;                        // [64][72]
    __half* Ks = sm + 64*72;                // [512][72]
    __half* Ps = sm;                        // [64][520]  (phase 2 overlay)
    __half* Vs = sm + 64*520;               // [512][72]  (phase 2)
    float* rmax = (float*)(sm + 70144);     // [64][4]
    float* rsum = rmax + 256;               // [64][4]

    int bh = blockIdx.y, b = bh >> 3, h = bh & 7;
    int q0 = blockIdx.x * 64;
    int tid = threadIdx.x, lane = tid & 31, wid = tid >> 5;
    int wm = wid & 3, wn = wid >> 2;        // 4 x 4
    int gid = lane >> 2, tig = lane & 3;

    {
        int r = tid >> 3, c = (tid & 7) * 8;
        cpa16(Qs + r*72 + c, qh + (size_t)(b*Sz + q0 + r)*Dm + h*DKh + c);
    }
    for (int idx = tid; idx < 4096; idx += 512) {
        int r = idx >> 3, c = (idx & 7) * 8;
        cpa16(Ks + r*72 + c, kh + (size_t)(b*Sz + r)*Dm + h*DKh + c);
    }
    CP_COMMIT();
    asm volatile("cp.async.wait_group 0;\n" ::: "memory");
    __syncthreads();

    // ---- phase 1: S = Q K^T (warp: 16 rows x 128 cols) ----
    float acc[16][4] = {};
#pragma unroll
    for (int kk = 0; kk < 4; kk++) {
        int kc = kk*16 + ((lane >> 4) << 3);
        uint32_t af[4];
        int ar = wm*16 + (lane & 15);
        ldsm4(af[0], af[1], af[2], af[3], Qs + ar*72 + kc);
#pragma unroll
        for (int ng = 0; ng < 8; ng++) {
            int br = wn*128 + ng*16 + (lane & 15);
            uint32_t r0, r1, r2, r3;
            ldsm4(r0, r1, r2, r3, Ks + br*72 + kc);
            uint32_t bf0[2] = {r0, r2}, bf1[2] = {r1, r3};
            mma_f16(acc[ng*2  ], af, bf0);
            mma_f16(acc[ng*2+1], af, bf1);
        }
    }
    __syncthreads();          // Qs/Ks dead

    // ---- V loads (overlap with softmax) ----
    for (int idx = tid; idx < 4096; idx += 512) {
        int r = idx >> 3, c = (idx & 7) * 8;
        cpa16(Vs + r*72 + c, vh + (size_t)(b*Sz + r)*Dm + h*DKh + c);
    }
    CP_COMMIT();

    // ---- softmax over regs ----
#pragma unroll
    for (int rh = 0; rh < 2; rh++) {
        float m1 = -INFINITY;
#pragma unroll
        for (int ni = 0; ni < 16; ni++)
#pragma unroll
            for (int nj = 0; nj < 2; nj++) {
                float v = acc[ni][rh*2+nj] * 0.125f;
                if (v == 0.f) v = NEGV;
                acc[ni][rh*2+nj] = v;
                m1 = fmaxf(m1, v);
            }
        m1 = fmaxf(m1, __shfl_xor_sync(0xffffffffu, m1, 1));
        m1 = fmaxf(m1, __shfl_xor_sync(0xffffffffu, m1, 2));
        int row = wm*16 + rh*8 + gid;
        if (tig == 0) rmax[row*4 + wn] = m1;
    }
    __syncthreads();
#pragma unroll
    for (int rh = 0; rh < 2; rh++) {
        int row = wm*16 + rh*8 + gid;
        float mx = fmaxf(fmaxf(rmax[row*4+0], rmax[row*4+1]),
                         fmaxf(rmax[row*4+2], rmax[row*4+3]));
        float s1 = 0.f;
#pragma unroll
        for (int ni = 0; ni < 16; ni++)
#pragma unroll
            for (int nj = 0; nj < 2; nj++) {
                float v = __expf(acc[ni][rh*2+nj] - mx);
                acc[ni][rh*2+nj] = v;
                s1 += v;
            }
        s1 += __shfl_xor_sync(0xffffffffu, s1, 1);
        s1 += __shfl_xor_sync(0xffffffffu, s1, 2);
        if (tig == 0) rsum[row*4 + wn] = s1;
    }
    __syncthreads();
    // ---- write P (fp16) into smem ----
#pragma unroll
    for (int rh = 0; rh < 2; rh++) {
        int row = wm*16 + rh*8 + gid;
        float inv = 1.f / (rsum[row*4+0] + rsum[row*4+1] + rsum[row*4+2] + rsum[row*4+3]);
#pragma unroll
        for (int ni = 0; ni < 16; ni++) {
            int col = wn*128 + ni*8 + tig*2;
            __half2 hv = __floats2half2_rn(acc[ni][rh*2+0] * inv,
                                           acc[ni][rh*2+1] * inv);
            *(__half2*)(Ps + row*520 + col) = hv;
        }
    }
    asm volatile("cp.async.wait_group 0;\n" ::: "memory");
    __syncthreads();

    // ---- phase 2: O = P V  (warp: 16 rows x 16 cols) ----
    float o[2][4] = {};
#pragma unroll 4
    for (int kk = 0; kk < 32; kk++) {
        int kc = kk*16 + ((lane >> 4) << 3);
        uint32_t af[4];
        int ar = wm*16 + (lane & 15);
        ldsm4(af[0], af[1], af[2], af[3], Ps + ar*520 + kc);
        uint32_t r0, r1, r2, r3;
        int rr = kk*16 + ((lane >> 4) << 3) + (lane & 7);
        int cc = wn*16 + (((lane >> 3) & 1) << 3);
        ldsm4t(r0, r1, r2, r3, Vs + rr*72 + cc);
        uint32_t bf0[2] = {r0, r2}, bf1[2] = {r1, r3};
        mma_f16(o[0], af, bf0);
        mma_f16(o[1], af, bf1);
    }

#pragma unroll
    for (int n8 = 0; n8 < 2; n8++) {
        int row = q0 + wm*16 + gid;
        int col = h*DKh + wn*16 + n8*8 + tig*2;
#pragma unroll
        for (int e2 = 0; e2 < 4; e2++) {
            int r  = row + (e2 >> 1)*8;
            int cc = col + (e2 & 1);
            attn[(size_t)(b*Sz + r)*Dm + cc] = o[n8][e2];
        }
    }
}

// ---------------- out = LayerNorm(a + res) (+ optional fp16 copy) -----------
template<int H16>
__global__ void add_ln(const float* __restrict__ a, const float* __restrict__ res,
                       const float* __restrict__ g, const float* __restrict__ beta,
                       float* __restrict__ out, __half* __restrict__ oh) {
    size_t row = blockIdx.x;
    int tid = threadIdx.x;
    int c = tid * 4;
    float4 av = *(const float4*)&a[row*Dm + c];
    float4 rv = *(const float4*)&res[row*Dm + c];
    float4 x;
    x.x = av.x + rv.x; x.y = av.y + rv.y; x.z = av.z + rv.z; x.w = av.w + rv.w;
    float s  = x.x + x.y + x.z + x.w;
    float s2 = x.x*x.x + x.y*x.y + x.z*x.z + x.w*x.w;
#pragma unroll
    for (int o = 16; o; o >>= 1) {
        s  += __shfl_xor_sync(0xffffffffu, s,  o);
        s2 += __shfl_xor_sync(0xffffffffu, s2, o);
    }
    __shared__ float sm[4], sq[4];
    if ((tid & 31) == 0) { sm[tid>>5] = s; sq[tid>>5] = s2; }
    __syncthreads();
    s  = sm[0] + sm[1] + sm[2] + sm[3];
    s2 = sq[0] + sq[1] + sq[2] + sq[3];
    float mean = s * (1.f/Dm);
    float var  = s2 * (1.f/Dm) - mean*mean;
    float inv  = rsqrtf(var + 1e-5f);
    float4 gv = *(const float4*)&g[c];
    float4 bv = *(const float4*)&beta[c];
    float y[4];
    y[0] = (x.x - mean)*inv*gv.x + bv.x;
    y[1] = (x.y - mean)*inv*gv.y + bv.y;
    y[2] = (x.z - mean)*inv*gv.z + bv.z;
    y[3] = (x.w - mean)*inv*gv.w + bv.w;
    *(float4*)&out[row*Dm + c] = *(float4*)y;
    if (H16) {
        __half2 h0 = __floats2half2_rn(y[0], y[1]);
        __half2 h1 = __floats2half2_rn(y[2], y[3]);
        *(__half2*)&oh[row*Dm + c]     = h0;
        *(__half2*)&oh[row*Dm + c + 2] = h1;
    }
}

// ---------------- decoder cross-attention (Sq=1, f32) ----------------
__global__ void cross_attn(const float* __restrict__ q, const float* __restrict__ k,
                           const float* __restrict__ v, float* __restrict__ o) {
    int h = blockIdx.x, b = blockIdx.y;
    __shared__ float qv[64];
    __shared__ float p[512];
    __shared__ float red[8];
    int tid = threadIdx.x;
    if (tid < 64) qv[tid] = q[b*Dm + h*DKh + tid];
    __syncthreads();
    float sc[2];
    float lmax = -INFINITY;
#pragma unroll
    for (int it = 0; it < 2; it++) {
        int j = tid + it*256;
        const float* kp = &k[(size_t)(b*Sz + j)*Dm + h*DKh];
        float s = 0.f;
#pragma unroll
        for (int c = 0; c < 64; c++) s += qv[c] * kp[c];
        s *= 0.125f;
        if (s == 0.f) s = NEGV;
        sc[it] = s;
        lmax = fmaxf(lmax, s);
    }
#pragma unroll
    for (int off = 16; off; off >>= 1) lmax = fmaxf(lmax, __shfl_xor_sync(0xffffffffu, lmax, off));
    if ((tid & 31) == 0) red[tid >> 5] = lmax;
    __syncthreads();
    float mx = red[0];
#pragma unroll
    for (int w = 1; w < 8; w++) mx = fmaxf(mx, red[w]);
    __syncthreads();
    float lsum = 0.f;
#pragma unroll
    for (int it = 0; it < 2; it++) {
        float e = __expf(sc[it] - mx);
        p[tid + it*256] = e;
        lsum += e;
    }
#pragma unroll
    for (int off = 16; off; off >>= 1) lsum += __shfl_xor_sync(0xffffffffu, lsum, off);
    if ((tid & 31) == 0) red[tid >> 5] = lsum;
    __syncthreads();
    float sum = red[0] + red[1] + red[2] + red[3] + red[4] + red[5] + red[6] + red[7];
    float inv = 1.f / sum;
    int warp = tid >> 5, lane = tid & 31;
#pragma unroll
    for (int dd = 0; dd < 8; dd++) {
        int d = warp*8 + dd;
        float acc = 0.f;
        for (int j = lane; j < Sz; j += 32)
            acc += p[j] * v[(size_t)(b*Sz + j)*Dm + h*DKh + d];
#pragma unroll
        for (int off = 16; off; off >>= 1) acc += __shfl_xor_sync(0xffffffffu, acc, off);
        if (lane == 0) o[b*Dm + h*DKh + d] = acc * inv;
    }
}

// ---------- tiny-M (M=8) GEMM, K-parallel: 512 thr = 64 cols x 8 K-slices ---
template<int RELU>
__global__ void __launch_bounds__(512)
gemm8w(const float* __restrict__ A, const float* __restrict__ W,
       const float* __restrict__ bias, float* __restrict__ C, int K, int N) {
    __shared__ float red[8][8][64];
    int t = threadIdx.x;
    int cl = t & 63;
    int col = blockIdx.x*64 + cl;
    int sl = t >> 6;
    float acc[8] = {};
    if (col < N) {
        int kn = K >> 3;
        int k0 = sl * kn, k1 = k0 + kn;
        for (int k = k0; k < k1; k++) {
            float wv = W[(size_t)k*N + col];
#pragma unroll
            for (int r = 0; r < 8; r++) acc[r] += A[r*K + k] * wv;
        }
    }
#pragma unroll
    for (int r = 0; r < 8; r++) red[r][sl][cl] = acc[r];
    __syncthreads();
    if (t < 64 && col < N) {
        float bv = bias[col];
#pragma unroll
        for (int r = 0; r < 8; r++) {
            float s = 0.f;
#pragma unroll
            for (int s8 = 0; s8 < 8; s8++) s += red[r][s8][t];
            float val = s + bv;
            if (RELU) val = fmaxf(val, 0.f);
            C[r*N + col] = val;
        }
    }
}

// ---------- fused LN + tiny-M GEMM: y = LN(a+res); state_out = y; C = y@W ---
// NO ARGUMENT MAY ALIAS: a, res, state_out, C must all be distinct buffers.
template<int RELU>
__global__ void __launch_bounds__(512)
gemm8w_ln(const float* __restrict__ a, const float* __restrict__ res,
          const float* __restrict__ g, const float* __restrict__ beta,
          float* __restrict__ state_out,
          const float* __restrict__ W, const float* __restrict__ bias,
          float* __restrict__ C, int N) {
    __shared__ float As[8][512];
    __shared__ float red[8][8][64];
    __shared__ float rs[16], rq[16];
    int t = threadIdx.x, lane = t & 31, wid = t >> 5;
    {
        int r = t >> 6, cb = (t & 63) * 8;
        float x[8];
        float s = 0.f, s2 = 0.f;
#pragma unroll
        for (int j = 0; j < 8; j++) {
            x[j] = a[r*Dm + cb + j] + res[r*Dm + cb + j];
            s += x[j]; s2 += x[j]*x[j];
        }
#pragma unroll
        for (int o = 16; o; o >>= 1) {
            s  += __shfl_xor_sync(0xffffffffu, s,  o);
            s2 += __shfl_xor_sync(0xffffffffu, s2, o);
        }
        if (lane == 0) { rs[wid] = s; rq[wid] = s2; }
        __syncthreads();
        s  = rs[r*2] + rs[r*2+1];
        s2 = rq[r*2] + rq[r*2+1];
        float mean = s * (1.f/Dm);
        float var  = s2 * (1.f/Dm) - mean*mean;
        float inv  = rsqrtf(var + 1e-5f);
#pragma unroll
        for (int j = 0; j < 8; j++) {
            float y = (x[j] - mean)*inv*g[cb+j] + beta[cb+j];
            As[r][cb+j] = y;
            state_out[r*Dm + cb + j] = y;
        }
    }
    __syncthreads();
    int cl = t & 63;
    int col = blockIdx.x*64 + cl;
    int sl = t >> 6;
    float acc[8] = {};
    if (col < N) {
        int k0 = sl * 64, k1 = k0 + 64;
        for (int k = k0; k < k1; k++) {
            float wv = W[(size_t)k*N + col];
#pragma unroll
            for (int r = 0; r < 8; r++) acc[r] += As[r][k] * wv;
        }
    }
#pragma unroll
    for (int r = 0; r < 8; r++) red[r][sl][cl] = acc[r];
    __syncthreads();
    if (t < 64 && col < N) {
        float bv = bias[col];
#pragma unroll
        for (int r = 0; r < 8; r++) {
            float s = 0.f;
#pragma unroll
            for (int s8 = 0; s8 < 8; s8++) s += red[r][s8][t];
            float val = s + bv;
            if (RELU) val = fmaxf(val, 0.f);
            C[r*N + col] = val;
        }
    }
}

// ---------------- host orchestration ----------------
extern "C" void kernel_launch(void* const* d_in, const int* in_sizes, int n_in,
                              void* d_out, int out_size) {
    const int*   x        = (const int*)d_in[0];
    const int*   tgt      = (const int*)d_in[1];
    const float* in_emb   = (const float*)d_in[2];
    const float* out_emb  = (const float*)d_in[3];
    const float* enc_qkv_w = (const float*)d_in[4];
    const float* enc_qkv_b = (const float*)d_in[5];
    const float* enc_ln1_g = (const float*)d_in[6];
    const float* enc_ln1_b = (const float*)d_in[7];
    const float* enc_ffn1_w = (const float*)d_in[8];
    const float* enc_ffn1_b = (const float*)d_in[9];
    const float* enc_ffn2_w = (const float*)d_in[10];
    const float* enc_ffn2_b = (const float*)d_in[11];
    const float* enc_ln2_g = (const float*)d_in[12];
    const float* enc_ln2_b = (const float*)d_in[13];
    const float* dec_qkv1_w = (const float*)d_in[14];
    const float* dec_qkv1_b = (const float*)d_in[15];
    const float* dec_ln1_g = (const float*)d_in[16];
    const float* dec_ln1_b = (const float*)d_in[17];
    const float* dec_qkv2_w = (const float*)d_in[18];
    const float* dec_qkv2_b = (const float*)d_in[19];
    const float* dec_ln2_g = (const float*)d_in[20];
    const float* dec_ln2_b = (const float*)d_in[21];
    const float* dec_ffn1_w = (const float*)d_in[22];
    const float* dec_ffn1_b = (const float*)d_in[23];
    const float* dec_ffn2_w = (const float*)d_in[24];
    const float* dec_ffn2_b = (const float*)d_in[25];
    const float* dec_ln3_g = (const float*)d_in[26];
    const float* dec_ln3_b = (const float*)d_in[27];
    const float* out_w = (const float*)d_in[28];
    const float* out_b = (const float*)d_in[29];

    float *e, *attn, *tbuf, *s0, *s1b, *dq, *dt, *dh, *kvf;
    __half *eh, *qkvh, *hh, *wqkvh, *wf1h, *wf2h, *wd2h;
    cudaGetSymbolAddress((void**)&e,    g_e);
    cudaGetSymbolAddress((void**)&eh,   g_eh);
    cudaGetSymbolAddress((void**)&qkvh, g_qkvh);
    cudaGetSymbolAddress((void**)&kvf,  g_kvf);
    cudaGetSymbolAddress((void**)&attn, g_attn);
    cudaGetSymbolAddress((void**)&hh,   g_hh);
    cudaGetSymbolAddress((void**)&tbuf, g_t);
    cudaGetSymbolAddress((void**)&s0,   g_d);
    cudaGetSymbolAddress((void**)&s1b,  g_s1);
    cudaGetSymbolAddress((void**)&dq,   g_dq);
    cudaGetSymbolAddress((void**)&dt,   g_dt);
    cudaGetSymbolAddress((void**)&dh,   g_dh);
    cudaGetSymbolAddress((void**)&wqkvh, g_wqkvh);
    cudaGetSymbolAddress((void**)&wf1h, g_wf1h);
    cudaGetSymbolAddress((void**)&wf2h, g_wf2h);
    cudaGetSymbolAddress((void**)&wd2h, g_wd2h);

    const int M = Bz*Sz;            // 4096
    const long long DD = (long long)Dm*Dm;
    const long long MD = (long long)M*Dm;

    const int SM_G128 = 30720 + 3*32*136*2;   // 56832
    const int SM_AT   = 70144*2 + 2048;       // 142336
    cudaFuncSetAttribute(gemm_mma<128,0,2>, cudaFuncAttributeMaxDynamicSharedMemorySize, SM_G128);
    cudaFuncSetAttribute(gemm_mma<128,1,2>, cudaFuncAttributeMaxDynamicSharedMemorySize, SM_G128);
    cudaFuncSetAttribute(gemm_mma<128,0,1>, cudaFuncAttributeMaxDynamicSharedMemorySize, SM_G128);
    cudaFuncSetAttribute(attn_fused,        cudaFuncAttributeMaxDynamicSharedMemorySize, SM_AT);

    const int CAP = 296;   // 2 CTAs/SM x 148 SMs

    // ---- convert all weights once, in a single launch ----
    {
        int n1 = Lz*3*Dm*Dm;
        int n2 = Lz*Dm*DFFz;
        long long total = 2LL*n1 + 2LL*n2;
        convh_all<<<(int)((total + 255)/256), 256>>>(
            enc_qkv_w, wqkvh, n1,
            enc_ffn1_w, wf1h, n2,
            enc_ffn2_w, wf2h, n2,
            dec_qkv2_w, wd2h, n1);
    }

    // ---------------- encoder ----------------
    embed_enc<<<(Bz*Sz*Dm + 255)/256, 256>>>(x, in_emb, e, eh);
    for (int i = 0; i < Lz; i++) {
        // QKV: tiles = 4 x 32 x 3 = 384 -> persistent over 296 CTAs
        gemm_mma<128,0,2><<<CAP, 256, SM_G128>>>(
            eh, wqkvh + (size_t)i*3*DD,
            enc_qkv_b + (size_t)i*3*Dm, nullptr, qkvh,
            Dm, Dm, Dm, Dm,
            Dm/128, M/128, 3,
            1, 0, 0, DD, 0, MD, 0, Dm, 0);
        attn_fused<<<dim3(Sz/64, Bz*Hn), 512, SM_AT>>>(
            qkvh, qkvh + MD, qkvh + 2*MD, attn);
        add_ln<1><<<M, 128>>>(attn, e, enc_ln1_g + i*Dm, enc_ln1_b + i*Dm, e, eh);
        // FFN1: tiles = 16 x 32 = 512
        gemm_mma<128,1,2><<<CAP, 256, SM_G128>>>(
            eh, wf1h + (size_t)i*Dm*DFFz,
            enc_ffn1_b + (size_t)i*DFFz, nullptr, hh,
            Dm, Dm, DFFz, DFFz,
            DFFz/128, M/128, 1,
            1, 0, 0, 0, 0, 0, 0, 0, 0);
        // FFN2: tiles = 4 x 32 = 128 (< CAP -> direct)
        gemm_mma<128,0,1><<<128, 256, SM_G128>>>(
            hh, wf2h + (size_t)i*DFFz*Dm,
            enc_ffn2_b + (size_t)i*Dm, tbuf, nullptr,
            DFFz, DFFz, Dm, Dm,
            Dm/128, M/128, 1,
            1, 0, 0, 0, 0, 0, 0, 0, 0);
        add_ln<1><<<M, 128>>>(tbuf, e, enc_ln2_g + i*Dm, enc_ln2_b + i*Dm, e, eh);
    }

    // ---- batched decoder cross K/V for ALL layers: tiles = 4 x 32 x 12 = 1536
    gemm_mma<128,0,1><<<CAP, 256, SM_G128>>>(
        eh, wd2h + DD,
        dec_qkv2_b + Dm, kvf, nullptr,
        Dm, Dm, Dm, Dm,
        Dm/128, M/128, Lz*2,
        2, 0, 0, 3*DD, DD, 2*MD, MD, 3*(long long)Dm, Dm);

    // ---------------- decoder (seq len 1; self-attn == V projection) --------
    float* s  = s0;
    float* ns = s1b;
    embed_dec<<<(Bz*Dm + 255)/256, 256>>>(tgt, out_emb, s);
    for (int i = 0; i < Lz; i++) {
        if (i == 0) {
            gemm8w<0><<<Dm/64, 512>>>(s, dec_qkv1_w + (size_t)(i*3+2)*DD,
                                      dec_qkv1_b + (i*3+2)*Dm, dh, Dm, Dm);
        } else {
            gemm8w_ln<0><<<Dm/64, 512>>>(dt, s, dec_ln3_g + (i-1)*Dm, dec_ln3_b + (i-1)*Dm,
                                         ns, dec_qkv1_w + (size_t)(i*3+2)*DD,
                                         dec_qkv1_b + (i*3+2)*Dm, dh, Dm);
            float* tmp = s; s = ns; ns = tmp;
        }
        gemm8w_ln<0><<<Dm/64, 512>>>(dh, s, dec_ln1_g + i*Dm, dec_ln1_b + i*Dm,
                                     ns, dec_qkv2_w + (size_t)(i*3+0)*DD,
                                     dec_qkv2_b + (i*3+0)*Dm, dq, Dm);
        { float* tmp = s; s = ns; ns = tmp; }
        cross_attn<<<dim3(Hn, Bz), 256>>>(dq, kvf + (size_t)i*2*MD, kvf + (size_t)i*2*MD + MD, dt);
        gemm8w_ln<1><<<DFFz/64, 512>>>(dt, s, dec_ln2_g + i*Dm, dec_ln2_b + i*Dm,
                                       ns, dec_ffn1_w + (size_t)i*Dm*DFFz,
                                       dec_ffn1_b + i*DFFz, dh, DFFz);
        { float* tmp = s; s = ns; ns = tmp; }
        gemm8w<0><<<Dm/64, 512>>>(dh, dec_ffn2_w + (size_t)i*DFFz*Dm,
                                  dec_ffn2_b + i*Dm, dt, DFFz, Dm);
    }
    gemm8w_ln<0><<<(OUTz+63)/64, 512>>>(dt, s, dec_ln3_g + (Lz-1)*Dm, dec_ln3_b + (Lz-1)*Dm,
                                        ns, out_w, out_b, (float*)d_out, OUTz);
    (void)in_sizes; (void)n_in; (void)out_size;
}

// round 16
// speedup vs baseline: 1.0246x; 1.0011x over previous
#include <cuda_runtime.h>
#include <cuda_fp16.h>
#include <math.h>
#include <stdint.h>

#define Bz   8
#define Sz   512
#define Dm   512
#define Hn   8
#define DKh  64
#define Lz   6
#define DFFz 2048
#define OUTz 1000
#define NEGV (-1e9f)

// ---------------- scratch (device globals) ----------------
__device__ float g_e[Bz*Sz*Dm];
__device__ __half g_eh[Bz*Sz*Dm];
__device__ __half g_qkvh[3*Bz*Sz*Dm];
__device__ float g_kvf[(size_t)Lz*2*Bz*Sz*Dm];
__device__ float g_attn[Bz*Sz*Dm];
__device__ __half g_hh[Bz*Sz*DFFz];
__device__ float g_t[Bz*Sz*Dm];
__device__ float g_d[Bz*Dm];
__device__ float g_s1[Bz*Dm];
__device__ float g_dq[Bz*Dm];
__device__ float g_dt[Bz*Dm];
__device__ float g_dh[Bz*DFFz];
// fp16 weights in original [K,N] layout
__device__ __half g_wqkvh[Lz*3*Dm*Dm];
__device__ __half g_wf1h[Lz*Dm*DFFz];
__device__ __half g_wf2h[Lz*DFFz*Dm];
__device__ __half g_wd2h[Lz*3*Dm*Dm];

// ---------------- helpers ----------------
__device__ __forceinline__ void cpa16(void* dst, const void* src) {
    uint32_t d = (uint32_t)__cvta_generic_to_shared(dst);
    asm volatile("cp.async.ca.shared.global [%0], [%1], 16;\n" :: "r"(d), "l"(src));
}
#define CP_COMMIT() asm volatile("cp.async.commit_group;\n" ::: "memory")
__device__ __forceinline__ void ldsm4(uint32_t& r0, uint32_t& r1, uint32_t& r2, uint32_t& r3,
                                      const void* p) {
    uint32_t a = (uint32_t)__cvta_generic_to_shared(p);
    asm volatile("ldmatrix.sync.aligned.m8n8.x4.shared.b16 {%0,%1,%2,%3}, [%4];\n"
                 : "=r"(r0), "=r"(r1), "=r"(r2), "=r"(r3) : "r"(a));
}
__device__ __forceinline__ void ldsm4t(uint32_t& r0, uint32_t& r1, uint32_t& r2, uint32_t& r3,
                                       const void* p) {
    uint32_t a = (uint32_t)__cvta_generic_to_shared(p);
    asm volatile("ldmatrix.sync.aligned.m8n8.x4.trans.shared.b16 {%0,%1,%2,%3}, [%4];\n"
                 : "=r"(r0), "=r"(r1), "=r"(r2), "=r"(r3) : "r"(a));
}
__device__ __forceinline__ void mma_f16(float c[4], const uint32_t a[4], const uint32_t b[2]) {
    asm volatile(
        "mma.sync.aligned.m16n8k16.row.col.f32.f16.f16.f32 "
        "{%0,%1,%2,%3}, {%4,%5,%6,%7}, {%8,%9}, {%0,%1,%2,%3};\n"
        : "+f"(c[0]), "+f"(c[1]), "+f"(c[2]), "+f"(c[3])
        : "r"(a[0]), "r"(a[1]), "r"(a[2]), "r"(a[3]), "r"(b[0]), "r"(b[1]));
}

// ---------------- convert 4 weight arrays f32 -> fp16 in one launch ---------
__global__ void convh_all(const float* __restrict__ s0, __half* __restrict__ d0, int n0,
                          const float* __restrict__ s1, __half* __restrict__ d1, int n1,
                          const float* __restrict__ s2, __half* __restrict__ d2, int n2,
                          const float* __restrict__ s3, __half* __restrict__ d3, int n3) {
    int i = blockIdx.x*blockDim.x + threadIdx.x;
    if (i < n0) { d0[i] = __float2half(s0[i]); return; }
    i -= n0;
    if (i < n1) { d1[i] = __float2half(s1[i]); return; }
    i -= n1;
    if (i < n2) { d2[i] = __float2half(s2[i]); return; }
    i -= n2;
    if (i < n3) { d3[i] = __float2half(s3[i]); }
}

// ---------------- embedding + PE ----------------
__global__ void embed_enc(const int* __restrict__ x, const float* __restrict__ emb,
                          float* __restrict__ e, __half* __restrict__ eh) {
    int idx = blockIdx.x*blockDim.x + threadIdx.x;
    if (idx >= Bz*Sz*Dm) return;
    int d  = idx % Dm;
    int bs = idx / Dm;
    int s  = bs % Sz;
    int tok = x[bs];
    float div = exp2f(-(float)(d & ~1) * (13.287712379549449f / (float)Dm));
    float arg = (float)s * div;
    float pe = (d & 1) ? cosf(arg) : sinf(arg);
    float v = emb[tok*Dm + d] * 22.627416997969522f + pe;
    e[idx] = v;
    eh[idx] = __float2half(v);
}

__global__ void embed_dec(const int* __restrict__ tgt, const float* __restrict__ emb,
                          float* __restrict__ o) {
    int idx = blockIdx.x*blockDim.x + threadIdx.x;
    if (idx >= Bz*Dm) return;
    int d = idx % Dm;
    int b = idx / Dm;
    float pe = (d & 1) ? 1.f : 0.f;
    o[idx] = emb[tgt[b]*Dm + d] * 22.627416997969522f + pe;
}

// ========== persistent 3-stage pipelined mma.sync GEMM (fp16) ===============
// Flattened tile loop over (gz, gy, gx); launch grid = min(total, cap).
template<int BN_, int EPI, int WMODE>
__global__ void __launch_bounds__(BN_ == 128 ? 256 : 128)
gemm_mma(const __half* __restrict__ Ag, const __half* __restrict__ Bg,
         const float* __restrict__ bias,
         float* __restrict__ C, __half* __restrict__ Ch,
         int K, int lda, int ldb, int ldc,
         int gx, int gy, int gz,
         int zdiv, long long sA1, long long sA2, long long sB1, long long sB2,
         long long sC1, long long sC2, long long sBias1, long long sBias2) {
    constexpr int NT   = (BN_ == 128) ? 256 : 128;
    constexpr int ASTG = 128 * 40;
    constexpr int BLD  = BN_ + 8;
    constexpr int BSTG = 32 * BLD;

    extern __shared__ __half sm[];
    __half* Ah = sm;
    __half* Bh = Ah + 3*ASTG;

    int tid = threadIdx.x, lane = tid & 31, wid = tid >> 5;
    int wm = wid & 1, wn = wid >> 1;
    int gid = lane >> 2, tig = lane & 3;
    const int KT = K >> 5;
    const int total = gx * gy * gz;

    for (int t = blockIdx.x; t < total; t += gridDim.x) {
        int z  = t / (gx * gy);
        int rem = t - z * gx * gy;
        int ty = rem / gx, tx = rem - ty * gx;
        int m0 = ty * 128, n0 = tx * BN_;
        int z1 = z / zdiv, z2 = z % zdiv;
        const __half* Ab = Ag + z1*sA1 + z2*sA2;
        const __half* Bb = Bg + z1*sB1 + z2*sB2;
        long long coff = z1*sC1 + z2*sC2;

        auto load_stage = [&](int st, int kt) {
            int k0 = kt * 32;
            for (int idx = tid; idx < 512; idx += NT) {
                int r = idx >> 2, c = (idx & 3) * 8;
                cpa16(Ah + st*ASTG + r*40 + c, Ab + (size_t)(m0 + r)*lda + k0 + c);
            }
            constexpr int CH = BN_ / 8;
            for (int idx = tid; idx < 32*CH; idx += NT) {
                int r = idx / CH, c = (idx % CH) * 8;
                cpa16(Bh + st*BSTG + r*BLD + c, Bb + (size_t)(k0 + r)*ldb + n0 + c);
            }
        };

        float acc[4][4][4] = {};

        load_stage(0, 0); CP_COMMIT();
        if (KT > 1) { load_stage(1, 1); CP_COMMIT(); }
        if (KT > 1) asm volatile("cp.async.wait_group 1;\n" ::: "memory");
        else        asm volatile("cp.async.wait_group 0;\n" ::: "memory");
        __syncthreads();

        for (int c = 0; c < KT; c++) {
            int st = c % 3;
            const __half* a_s = Ah + st*ASTG;
            const __half* b_s = Bh + st*BSTG;

#pragma unroll
            for (int kk = 0; kk < 2; kk++) {
                int kc = kk*16 + ((lane >> 4) << 3);
                uint32_t af[4][4], bf[4][2];
#pragma unroll
                for (int mi = 0; mi < 4; mi++) {
                    int ar = wm*64 + mi*16 + (lane & 15);
                    ldsm4(af[mi][0], af[mi][1], af[mi][2], af[mi][3], a_s + ar*40 + kc);
                }
#pragma unroll
                for (int ng = 0; ng < 2; ng++) {
                    uint32_t r0, r1, r2, r3;
                    int rr = kk*16 + ((lane >> 4) << 3) + (lane & 7);
                    int cc = wn*32 + ng*16 + (((lane >> 3) & 1) << 3);
                    ldsm4t(r0, r1, r2, r3, b_s + rr*BLD + cc);
                    bf[ng*2  ][0] = r0; bf[ng*2  ][1] = r2;
                    bf[ng*2+1][0] = r1; bf[ng*2+1][1] = r3;
                }
#pragma unroll
                for (int mi = 0; mi < 4; mi++)
#pragma unroll
                    for (int ni = 0; ni < 4; ni++) mma_f16(acc[mi][ni], af[mi], bf[ni]);
            }

            if (c + 2 < KT) {
                load_stage((c + 2) % 3, c + 2);
                CP_COMMIT();
                asm volatile("cp.async.wait_group 1;\n" ::: "memory");
                __syncthreads();
            } else if (c + 1 < KT) {
                asm volatile("cp.async.wait_group 0;\n" ::: "memory");
                __syncthreads();
            }
        }

        const float* biasb = (EPI <= 1) ? bias + z1*sBias1 + z2*sBias2 : nullptr;
#pragma unroll
        for (int mi = 0; mi < 4; mi++)
#pragma unroll
            for (int ni = 0; ni < 4; ni++) {
                int row = m0 + wm*64 + mi*16 + gid;
                int col = n0 + wn*32 + ni*8 + tig*2;
#pragma unroll
                for (int e2 = 0; e2 < 4; e2++) {
                    int r  = row + (e2 >> 1)*8;
                    int cc = col + (e2 & 1);
                    float v = acc[mi][ni][e2];
                    if (EPI == 0 || EPI == 1) v += biasb[cc];
                    if (EPI == 1) v = fmaxf(v, 0.f);
                    size_t idx = (size_t)(coff + (long long)r*ldc + cc);
                    if (WMODE & 1) C[idx] = v;
                    if (WMODE & 2) Ch[idx] = __float2half(v);
                }
            }
        __syncthreads();   // epilogue done before next tile overwrites smem
    }
}

// ============ fused attention, 512 threads (16 warps: 4m x 4n) ==============
__global__ void __launch_bounds__(512)
attn_fused(const __half* __restrict__ qh, const __half* __restrict__ kh,
           const __half* __restrict__ vh, float* __restrict__ attn) {
    extern __shared__ __half sm[];
    __half* Qs = sm;                        // [64][72]
    __half* Ks = sm + 64*72;                // [512][72]
    __half* Ps = sm;                        // [64][520]  (phase 2 overlay)
    __half* Vs = sm + 64*520;               // [512][72]  (phase 2)
    float* rmax = (float*)(sm + 70144);     // [64][4]
    float* rsum = rmax + 256;               // [64][4]

    int bh = blockIdx.y, b = bh >> 3, h = bh & 7;
    int q0 = blockIdx.x * 64;
    int tid = threadIdx.x, lane = tid & 31, wid = tid >> 5;
    int wm = wid & 3, wn = wid >> 2;        // 4 x 4
    int gid = lane >> 2, tig = lane & 3;

    {
        int r = tid >> 3, c = (tid & 7) * 8;
        cpa16(Qs + r*72 + c, qh + (size_t)(b*Sz + q0 + r)*Dm + h*DKh + c);
    }
    for (int idx = tid; idx < 4096; idx += 512) {
        int r = idx >> 3, c = (idx & 7) * 8;
        cpa16(Ks + r*72 + c, kh + (size_t)(b*Sz + r)*Dm + h*DKh + c);
    }
    CP_COMMIT();
    asm volatile("cp.async.wait_group 0;\n" ::: "memory");
    __syncthreads();

    // ---- phase 1: S = Q K^T (warp: 16 rows x 128 cols) ----
    float acc[16][4] = {};
#pragma unroll
    for (int kk = 0; kk < 4; kk++) {
        int kc = kk*16 + ((lane >> 4) << 3);
        uint32_t af[4];
        int ar = wm*16 + (lane & 15);
        ldsm4(af[0], af[1], af[2], af[3], Qs + ar*72 + kc);
#pragma unroll
        for (int ng = 0; ng < 8; ng++) {
            int br = wn*128 + ng*16 + (lane & 15);
            uint32_t r0, r1, r2, r3;
            ldsm4(r0, r1, r2, r3, Ks + br*72 + kc);
            uint32_t bf0[2] = {r0, r2}, bf1[2] = {r1, r3};
            mma_f16(acc[ng*2  ], af, bf0);
            mma_f16(acc[ng*2+1], af, bf1);
        }
    }
    __syncthreads();          // Qs/Ks dead

    // ---- V loads (overlap with softmax) ----
    for (int idx = tid; idx < 4096; idx += 512) {
        int r = idx >> 3, c = (idx & 7) * 8;
        cpa16(Vs + r*72 + c, vh + (size_t)(b*Sz + r)*Dm + h*DKh + c);
    }
    CP_COMMIT();

    // ---- softmax over regs ----
#pragma unroll
    for (int rh = 0; rh < 2; rh++) {
        float m1 = -INFINITY;
#pragma unroll
        for (int ni = 0; ni < 16; ni++)
#pragma unroll
            for (int nj = 0; nj < 2; nj++) {
                float v = acc[ni][rh*2+nj] * 0.125f;
                if (v == 0.f) v = NEGV;
                acc[ni][rh*2+nj] = v;
                m1 = fmaxf(m1, v);
            }
        m1 = fmaxf(m1, __shfl_xor_sync(0xffffffffu, m1, 1));
        m1 = fmaxf(m1, __shfl_xor_sync(0xffffffffu, m1, 2));
        int row = wm*16 + rh*8 + gid;
        if (tig == 0) rmax[row*4 + wn] = m1;
    }
    __syncthreads();
#pragma unroll
    for (int rh = 0; rh < 2; rh++) {
        int row = wm*16 + rh*8 + gid;
        float mx = fmaxf(fmaxf(rmax[row*4+0], rmax[row*4+1]),
                         fmaxf(rmax[row*4+2], rmax[row*4+3]));
        float s1 = 0.f;
#pragma unroll
        for (int ni = 0; ni < 16; ni++)
#pragma unroll
            for (int nj = 0; nj < 2; nj++) {
                float v = __expf(acc[ni][rh*2+nj] - mx);
                acc[ni][rh*2+nj] = v;
                s1 += v;
            }
        s1 += __shfl_xor_sync(0xffffffffu, s1, 1);
        s1 += __shfl_xor_sync(0xffffffffu, s1, 2);
        if (tig == 0) rsum[row*4 + wn] = s1;
    }
    __syncthreads();
    // ---- write P (fp16) into smem ----
#pragma unroll
    for (int rh = 0; rh < 2; rh++) {
        int row = wm*16 + rh*8 + gid;
        float inv = 1.f / (rsum[row*4+0] + rsum[row*4+1] + rsum[row*4+2] + rsum[row*4+3]);
#pragma unroll
        for (int ni = 0; ni < 16; ni++) {
            int col = wn*128 + ni*8 + tig*2;
            __half2 hv = __floats2half2_rn(acc[ni][rh*2+0] * inv,
                                           acc[ni][rh*2+1] * inv);
            *(__half2*)(Ps + row*520 + col) = hv;
        }
    }
    asm volatile("cp.async.wait_group 0;\n" ::: "memory");
    __syncthreads();

    // ---- phase 2: O = P V  (warp: 16 rows x 16 cols) ----
    float o[2][4] = {};
#pragma unroll 4
    for (int kk = 0; kk < 32; kk++) {
        int kc = kk*16 + ((lane >> 4) << 3);
        uint32_t af[4];
        int ar = wm*16 + (lane & 15);
        ldsm4(af[0], af[1], af[2], af[3], Ps + ar*520 + kc);
        uint32_t r0, r1, r2, r3;
        int rr = kk*16 + ((lane >> 4) << 3) + (lane & 7);
        int cc = wn*16 + (((lane >> 3) & 1) << 3);
        ldsm4t(r0, r1, r2, r3, Vs + rr*72 + cc);
        uint32_t bf0[2] = {r0, r2}, bf1[2] = {r1, r3};
        mma_f16(o[0], af, bf0);
        mma_f16(o[1], af, bf1);
    }

#pragma unroll
    for (int n8 = 0; n8 < 2; n8++) {
        int row = q0 + wm*16 + gid;
        int col = h*DKh + wn*16 + n8*8 + tig*2;
#pragma unroll
        for (int e2 = 0; e2 < 4; e2++) {
            int r  = row + (e2 >> 1)*8;
            int cc = col + (e2 & 1);
            attn[(size_t)(b*Sz + r)*Dm + cc] = o[n8][e2];
        }
    }
}

// ---------------- out = LayerNorm(a + res) (+ optional fp16 copy) -----------
template<int H16>
__global__ void add_ln(const float* __restrict__ a, const float* __restrict__ res,
                       const float* __restrict__ g, const float* __restrict__ beta,
                       float* __restrict__ out, __half* __restrict__ oh) {
    size_t row = blockIdx.x;
    int tid = threadIdx.x;
    int c = tid * 4;
    float4 av = *(const float4*)&a[row*Dm + c];
    float4 rv = *(const float4*)&res[row*Dm + c];
    float4 x;
    x.x = av.x + rv.x; x.y = av.y + rv.y; x.z = av.z + rv.z; x.w = av.w + rv.w;
    float s  = x.x + x.y + x.z + x.w;
    float s2 = x.x*x.x + x.y*x.y + x.z*x.z + x.w*x.w;
#pragma unroll
    for (int o = 16; o; o >>= 1) {
        s  += __shfl_xor_sync(0xffffffffu, s,  o);
        s2 += __shfl_xor_sync(0xffffffffu, s2, o);
    }
    __shared__ float sm[4], sq[4];
    if ((tid & 31) == 0) { sm[tid>>5] = s; sq[tid>>5] = s2; }
    __syncthreads();
    s  = sm[0] + sm[1] + sm[2] + sm[3];
    s2 = sq[0] + sq[1] + sq[2] + sq[3];
    float mean = s * (1.f/Dm);
    float var  = s2 * (1.f/Dm) - mean*mean;
    float inv  = rsqrtf(var + 1e-5f);
    float4 gv = *(const float4*)&g[c];
    float4 bv = *(const float4*)&beta[c];
    float y[4];
    y[0] = (x.x - mean)*inv*gv.x + bv.x;
    y[1] = (x.y - mean)*inv*gv.y + bv.y;
    y[2] = (x.z - mean)*inv*gv.z + bv.z;
    y[3] = (x.w - mean)*inv*gv.w + bv.w;
    *(float4*)&out[row*Dm + c] = *(float4*)y;
    if (H16) {
        __half2 h0 = __floats2half2_rn(y[0], y[1]);
        __half2 h1 = __floats2half2_rn(y[2], y[3]);
        *(__half2*)&oh[row*Dm + c]     = h0;
        *(__half2*)&oh[row*Dm + c + 2] = h1;
    }
}

// ---------------- decoder cross-attention (Sq=1, f32) ----------------
__global__ void cross_attn(const float* __restrict__ q, const float* __restrict__ k,
                           const float* __restrict__ v, float* __restrict__ o) {
    int h = blockIdx.x, b = blockIdx.y;
    __shared__ float qv[64];
    __shared__ float p[512];
    __shared__ float red[8];
    int tid = threadIdx.x;
    if (tid < 64) qv[tid] = q[b*Dm + h*DKh + tid];
    __syncthreads();
    float sc[2];
    float lmax = -INFINITY;
#pragma unroll
    for (int it = 0; it < 2; it++) {
        int j = tid + it*256;
        const float* kp = &k[(size_t)(b*Sz + j)*Dm + h*DKh];
        float s = 0.f;
#pragma unroll
        for (int c = 0; c < 64; c++) s += qv[c] * kp[c];
        s *= 0.125f;
        if (s == 0.f) s = NEGV;
        sc[it] = s;
        lmax = fmaxf(lmax, s);
    }
#pragma unroll
    for (int off = 16; off; off >>= 1) lmax = fmaxf(lmax, __shfl_xor_sync(0xffffffffu, lmax, off));
    if ((tid & 31) == 0) red[tid >> 5] = lmax;
    __syncthreads();
    float mx = red[0];
#pragma unroll
    for (int w = 1; w < 8; w++) mx = fmaxf(mx, red[w]);
    __syncthreads();
    float lsum = 0.f;
#pragma unroll
    for (int it = 0; it < 2; it++) {
        float e = __expf(sc[it] - mx);
        p[tid + it*256] = e;
        lsum += e;
    }
#pragma unroll
    for (int off = 16; off; off >>= 1) lsum += __shfl_xor_sync(0xffffffffu, lsum, off);
    if ((tid & 31) == 0) red[tid >> 5] = lsum;
    __syncthreads();
    float sum = red[0] + red[1] + red[2] + red[3] + red[4] + red[5] + red[6] + red[7];
    float inv = 1.f / sum;
    int warp = tid >> 5, lane = tid & 31;
#pragma unroll
    for (int dd = 0; dd < 8; dd++) {
        int d = warp*8 + dd;
        float acc = 0.f;
        for (int j = lane; j < Sz; j += 32)
            acc += p[j] * v[(size_t)(b*Sz + j)*Dm + h*DKh + d];
#pragma unroll
        for (int off = 16; off; off >>= 1) acc += __shfl_xor_sync(0xffffffffu, acc, off);
        if (lane == 0) o[b*Dm + h*DKh + d] = acc * inv;
    }
}

// ---------- tiny-M (M=8) GEMM, K-parallel: 512 thr = 64 cols x 8 K-slices ---
template<int RELU>
__global__ void __launch_bounds__(512)
gemm8w(const float* __restrict__ A, const float* __restrict__ W,
       const float* __restrict__ bias, float* __restrict__ C, int K, int N) {
    __shared__ float red[8][8][64];
    int t = threadIdx.x;
    int cl = t & 63;
    int col = blockIdx.x*64 + cl;
    int sl = t >> 6;
    float acc[8] = {};
    if (col < N) {
        int kn = K >> 3;
        int k0 = sl * kn, k1 = k0 + kn;
        for (int k = k0; k < k1; k++) {
            float wv = W[(size_t)k*N + col];
#pragma unroll
            for (int r = 0; r < 8; r++) acc[r] += A[r*K + k] * wv;
        }
    }
#pragma unroll
    for (int r = 0; r < 8; r++) red[r][sl][cl] = acc[r];
    __syncthreads();
    if (t < 64 && col < N) {
        float bv = bias[col];
#pragma unroll
        for (int r = 0; r < 8; r++) {
            float s = 0.f;
#pragma unroll
            for (int s8 = 0; s8 < 8; s8++) s += red[r][s8][t];
            float val = s + bv;
            if (RELU) val = fmaxf(val, 0.f);
            C[r*N + col] = val;
        }
    }
}

// ---------- fused LN + tiny-M GEMM: y = LN(a+res); state_out = y; C = y@W ---
// NO ARGUMENT MAY ALIAS: a, res, state_out, C must all be distinct buffers.
template<int RELU>
__global__ void __launch_bounds__(512)
gemm8w_ln(const float* __restrict__ a, const float* __restrict__ res,
          const float* __restrict__ g, const float* __restrict__ beta,
          float* __restrict__ state_out,
          const float* __restrict__ W, const float* __restrict__ bias,
          float* __restrict__ C, int N) {
    __shared__ float As[8][512];
    __shared__ float red[8][8][64];
    __shared__ float rs[16], rq[16];
    int t = threadIdx.x, lane = t & 31, wid = t >> 5;
    {
        int r = t >> 6, cb = (t & 63) * 8;
        float x[8];
        float s = 0.f, s2 = 0.f;
#pragma unroll
        for (int j = 0; j < 8; j++) {
            x[j] = a[r*Dm + cb + j] + res[r*Dm + cb + j];
            s += x[j]; s2 += x[j]*x[j];
        }
#pragma unroll
        for (int o = 16; o; o >>= 1) {
            s  += __shfl_xor_sync(0xffffffffu, s,  o);
            s2 += __shfl_xor_sync(0xffffffffu, s2, o);
        }
        if (lane == 0) { rs[wid] = s; rq[wid] = s2; }
        __syncthreads();
        s  = rs[r*2] + rs[r*2+1];
        s2 = rq[r*2] + rq[r*2+1];
        float mean = s * (1.f/Dm);
        float var  = s2 * (1.f/Dm) - mean*mean;
        float inv  = rsqrtf(var + 1e-5f);
#pragma unroll
        for (int j = 0; j < 8; j++) {
            float y = (x[j] - mean)*inv*g[cb+j] + beta[cb+j];
            As[r][cb+j] = y;
            state_out[r*Dm + cb + j] = y;
        }
    }
    __syncthreads();
    int cl = t & 63;
    int col = blockIdx.x*64 + cl;
    int sl = t >> 6;
    float acc[8] = {};
    if (col < N) {
        int k0 = sl * 64, k1 = k0 + 64;
        for (int k = k0; k < k1; k++) {
            float wv = W[(size_t)k*N + col];
#pragma unroll
            for (int r = 0; r < 8; r++) acc[r] += As[r][k] * wv;
        }
    }
#pragma unroll
    for (int r = 0; r < 8; r++) red[r][sl][cl] = acc[r];
    __syncthreads();
    if (t < 64 && col < N) {
        float bv = bias[col];
#pragma unroll
        for (int r = 0; r < 8; r++) {
            float s = 0.f;
#pragma unroll
            for (int s8 = 0; s8 < 8; s8++) s += red[r][s8][t];
            float val = s + bv;
            if (RELU) val = fmaxf(val, 0.f);
            C[r*N + col] = val;
        }
    }
}

// ---------------- host orchestration ----------------
extern "C" void kernel_launch(void* const* d_in, const int* in_sizes, int n_in,
                              void* d_out, int out_size) {
    const int*   x        = (const int*)d_in[0];
    const int*   tgt      = (const int*)d_in[1];
    const float* in_emb   = (const float*)d_in[2];
    const float* out_emb  = (const float*)d_in[3];
    const float* enc_qkv_w = (const float*)d_in[4];
    const float* enc_qkv_b = (const float*)d_in[5];
    const float* enc_ln1_g = (const float*)d_in[6];
    const float* enc_ln1_b = (const float*)d_in[7];
    const float* enc_ffn1_w = (const float*)d_in[8];
    const float* enc_ffn1_b = (const float*)d_in[9];
    const float* enc_ffn2_w = (const float*)d_in[10];
    const float* enc_ffn2_b = (const float*)d_in[11];
    const float* enc_ln2_g = (const float*)d_in[12];
    const float* enc_ln2_b = (const float*)d_in[13];
    const float* dec_qkv1_w = (const float*)d_in[14];
    const float* dec_qkv1_b = (const float*)d_in[15];
    const float* dec_ln1_g = (const float*)d_in[16];
    const float* dec_ln1_b = (const float*)d_in[17];
    const float* dec_qkv2_w = (const float*)d_in[18];
    const float* dec_qkv2_b = (const float*)d_in[19];
    const float* dec_ln2_g = (const float*)d_in[20];
    const float* dec_ln2_b = (const float*)d_in[21];
    const float* dec_ffn1_w = (const float*)d_in[22];
    const float* dec_ffn1_b = (const float*)d_in[23];
    const float* dec_ffn2_w = (const float*)d_in[24];
    const float* dec_ffn2_b = (const float*)d_in[25];
    const float* dec_ln3_g = (const float*)d_in[26];
    const float* dec_ln3_b = (const float*)d_in[27];
    const float* out_w = (const float*)d_in[28];
    const float* out_b = (const float*)d_in[29];

    float *e, *attn, *tbuf, *s0, *s1b, *dq, *dt, *dh, *kvf;
    __half *eh, *qkvh, *hh, *wqkvh, *wf1h, *wf2h, *wd2h;
    cudaGetSymbolAddress((void**)&e,    g_e);
    cudaGetSymbolAddress((void**)&eh,   g_eh);
    cudaGetSymbolAddress((void**)&qkvh, g_qkvh);
    cudaGetSymbolAddress((void**)&kvf,  g_kvf);
    cudaGetSymbolAddress((void**)&attn, g_attn);
    cudaGetSymbolAddress((void**)&hh,   g_hh);
    cudaGetSymbolAddress((void**)&tbuf, g_t);
    cudaGetSymbolAddress((void**)&s0,   g_d);
    cudaGetSymbolAddress((void**)&s1b,  g_s1);
    cudaGetSymbolAddress((void**)&dq,   g_dq);
    cudaGetSymbolAddress((void**)&dt,   g_dt);
    cudaGetSymbolAddress((void**)&dh,   g_dh);
    cudaGetSymbolAddress((void**)&wqkvh, g_wqkvh);
    cudaGetSymbolAddress((void**)&wf1h, g_wf1h);
    cudaGetSymbolAddress((void**)&wf2h, g_wf2h);
    cudaGetSymbolAddress((void**)&wd2h, g_wd2h);

    const int M = Bz*Sz;            // 4096
    const long long DD = (long long)Dm*Dm;
    const long long MD = (long long)M*Dm;

    const int SM_G128 = 30720 + 3*32*136*2;   // 56832
    const int SM_AT   = 70144*2 + 2048;       // 142336
    cudaFuncSetAttribute(gemm_mma<128,0,2>, cudaFuncAttributeMaxDynamicSharedMemorySize, SM_G128);
    cudaFuncSetAttribute(gemm_mma<128,1,2>, cudaFuncAttributeMaxDynamicSharedMemorySize, SM_G128);
    cudaFuncSetAttribute(gemm_mma<128,0,1>, cudaFuncAttributeMaxDynamicSharedMemorySize, SM_G128);
    cudaFuncSetAttribute(attn_fused,        cudaFuncAttributeMaxDynamicSharedMemorySize, SM_AT);

    const int CAP = 296;   // 2 CTAs/SM x 148 SMs

    // ---- convert all weights once, in a single launch ----
    {
        int n1 = Lz*3*Dm*Dm;
        int n2 = Lz*Dm*DFFz;
        long long total = 2LL*n1 + 2LL*n2;
        convh_all<<<(int)((total + 255)/256), 256>>>(
            enc_qkv_w, wqkvh, n1,
            enc_ffn1_w, wf1h, n2,
            enc_ffn2_w, wf2h, n2,
            dec_qkv2_w, wd2h, n1);
    }

    // ---------------- encoder ----------------
    embed_enc<<<(Bz*Sz*Dm + 255)/256, 256>>>(x, in_emb, e, eh);
    for (int i = 0; i < Lz; i++) {
        // QKV: tiles = 4 x 32 x 3 = 384 -> persistent over 296 CTAs
        gemm_mma<128,0,2><<<CAP, 256, SM_G128>>>(
            eh, wqkvh + (size_t)i*3*DD,
            enc_qkv_b + (size_t)i*3*Dm, nullptr, qkvh,
            Dm, Dm, Dm, Dm,
            Dm/128, M/128, 3,
            1, 0, 0, DD, 0, MD, 0, Dm, 0);
        attn_fused<<<dim3(Sz/64, Bz*Hn), 512, SM_AT>>>(
            qkvh, qkvh + MD, qkvh + 2*MD, attn);
        add_ln<1><<<M, 128>>>(attn, e, enc_ln1_g + i*Dm, enc_ln1_b + i*Dm, e, eh);
        // FFN1: tiles = 16 x 32 = 512
        gemm_mma<128,1,2><<<CAP, 256, SM_G128>>>(
            eh, wf1h + (size_t)i*Dm*DFFz,
            enc_ffn1_b + (size_t)i*DFFz, nullptr, hh,
            Dm, Dm, DFFz, DFFz,
            DFFz/128, M/128, 1,
            1, 0, 0, 0, 0, 0, 0, 0, 0);
        // FFN2: tiles = 4 x 32 = 128 (< CAP -> direct)
        gemm_mma<128,0,1><<<128, 256, SM_G128>>>(
            hh, wf2h + (size_t)i*DFFz*Dm,
            enc_ffn2_b + (size_t)i*Dm, tbuf, nullptr,
            DFFz, DFFz, Dm, Dm,
            Dm/128, M/128, 1,
            1, 0, 0, 0, 0, 0, 0, 0, 0);
        add_ln<1><<<M, 128>>>(tbuf, e, enc_ln2_g + i*Dm, enc_ln2_b + i*Dm, e, eh);
    }

    // ---- batched decoder cross K/V for ALL layers: tiles = 4 x 32 x 12 = 1536
    gemm_mma<128,0,1><<<CAP, 256, SM_G128>>>(
        eh, wd2h + DD,
        dec_qkv2_b + Dm, kvf, nullptr,
        Dm, Dm, Dm, Dm,
        Dm/128, M/128, Lz*2,
        2, 0, 0, 3*DD, DD, 2*MD, MD, 3*(long long)Dm, Dm);

    // ---------------- decoder (seq len 1; self-attn == V projection) --------
    float* s  = s0;
    float* ns = s1b;
    embed_dec<<<(Bz*Dm + 255)/256, 256>>>(tgt, out_emb, s);
    for (int i = 0; i < Lz; i++) {
        if (i == 0) {
            gemm8w<0><<<Dm/64, 512>>>(s, dec_qkv1_w + (size_t)(i*3+2)*DD,
                                      dec_qkv1_b + (i*3+2)*Dm, dh, Dm, Dm);
        } else {
            gemm8w_ln<0><<<Dm/64, 512>>>(dt, s, dec_ln3_g + (i-1)*Dm, dec_ln3_b + (i-1)*Dm,
                                         ns, dec_qkv1_w + (size_t)(i*3+2)*DD,
                                         dec_qkv1_b + (i*3+2)*Dm, dh, Dm);
            float* tmp = s; s = ns; ns = tmp;
        }
        gemm8w_ln<0><<<Dm/64, 512>>>(dh, s, dec_ln1_g + i*Dm, dec_ln1_b + i*Dm,
                                     ns, dec_qkv2_w + (size_t)(i*3+0)*DD,
                                     dec_qkv2_b + (i*3+0)*Dm, dq, Dm);
        { float* tmp = s; s = ns; ns = tmp; }
        cross_attn<<<dim3(Hn, Bz), 256>>>(dq, kvf + (size_t)i*2*MD, kvf + (size_t)i*2*MD + MD, dt);
        gemm8w_ln<1><<<DFFz/64, 512>>>(dt, s, dec_ln2_g + i*Dm, dec_ln2_b + i*Dm,
                                       ns, dec_ffn1_w + (size_t)i*Dm*DFFz,
                                       dec_ffn1_b + i*DFFz, dh, DFFz);
        { float* tmp = s; s = ns; ns = tmp; }
        gemm8w<0><<<Dm/64, 512>>>(dh, dec_ffn2_w + (size_t)i*DFFz*Dm,
                                  dec_ffn2_b + i*Dm, dt, DFFz, Dm);
    }
    gemm8w_ln<0><<<(OUTz+63)/64, 512>>>(dt, s, dec_ln3_g + (Lz-1)*Dm, dec_ln3_b + (Lz-1)*Dm,
                                        ns, out_w, out_b, (float*)d_out, OUTz);
    (void)in_sizes; (void)n_in; (void)out_size;
}